// round 1
// baseline (speedup 1.0000x reference)
#include <cuda_runtime.h>

typedef unsigned long long ull;

#define NP      250000
#define NATOMS  10000
#define HH      128
#define NBLK    5
#define TILE    128
#define NTHR    256
#define XS      132            // padded row stride for [feat][row] smem tiles

// ---------------- device scratch (no allocation allowed) ----------------
__device__ float g_blockout[NBLK * NATOMS * 2];   // per-block segment sums
__device__ float g_nh;                            // nhloss accumulator

// ---------------- helpers ----------------
__device__ __forceinline__ ull pack2(float x) {
    ull d; asm("mov.b64 %0, {%1, %1};" : "=l"(d) : "f"(x)); return d;
}
__device__ __forceinline__ ull ffma2(ull a, ull b, ull c) {
    ull d; asm("fma.rn.f32x2 %0, %1, %2, %3;" : "=l"(d) : "l"(a), "l"(b), "l"(c)); return d;
}
__device__ __forceinline__ void unpack2(ull v, float& lo, float& hi) {
    asm("mov.b64 {%0, %1}, %2;" : "=f"(lo), "=f"(hi) : "l"(v));
}
// shifted softplus: softplus(x) - ln2, numerically stable, fast intrinsics
// (abs error ~3e-7, fine for 1e-3 tolerance)
__device__ __forceinline__ float sspf(float x) {
    float e = __expf(-fabsf(x));
    return fmaxf(x, 0.0f) + __logf(1.0f + e) - 0.69314718055994531f;
}

// ---------------- 128x128x128 fused GEMM + bias + ssp ----------------
// Xin/Xout are feature-major smem tiles: X[k*XS + r]. Safe for Xin==Xout.
// W global row-major [k][c]; panel-staged through Ws smem.
__device__ __noinline__ void gemm128_ssp(
    const float* __restrict__ Wg, const float* __restrict__ Bg,
    const float* Xin, float* Xout, float* Ws, int tid)
{
    const int tx = tid & 15, ty = tid >> 4;
    const int c0 = tx * 8, r0 = ty * 8;

    ull acc[8][4];
    #pragma unroll
    for (int i = 0; i < 8; ++i)
        #pragma unroll
        for (int j = 0; j < 4; ++j) acc[i][j] = 0ull;

    #pragma unroll 1
    for (int kp = 0; kp < 4; ++kp) {
        // stage 32-row W panel into smem
        const float4* Wg4 = reinterpret_cast<const float4*>(Wg + kp * 32 * HH);
        #pragma unroll
        for (int j = 0; j < 4; ++j) {
            int t  = tid + j * NTHR;       // 0..1023
            int i  = t >> 5;               // panel row 0..31
            int c4 = t & 31;               // float4 column
            float4 v = Wg4[i * 32 + c4];
            *reinterpret_cast<float4*>(&Ws[i * XS + c4 * 4]) = v;
        }
        __syncthreads();

        #pragma unroll
        for (int kk = 0; kk < 32; ++kk) {
            const float* xr = &Xin[(kp * 32 + kk) * XS + r0];
            float4 xa = *reinterpret_cast<const float4*>(xr);
            float4 xb = *reinterpret_cast<const float4*>(xr + 4);
            const ulonglong2* wr =
                reinterpret_cast<const ulonglong2*>(&Ws[kk * XS + c0]);
            ulonglong2 wA = wr[0];   // cols c0..c0+3 as two f32x2
            ulonglong2 wB = wr[1];   // cols c0+4..c0+7

            ull x0 = pack2(xa.x), x1 = pack2(xa.y), x2 = pack2(xa.z), x3 = pack2(xa.w);
            ull x4 = pack2(xb.x), x5 = pack2(xb.y), x6 = pack2(xb.z), x7 = pack2(xb.w);

            acc[0][0]=ffma2(x0,wA.x,acc[0][0]); acc[0][1]=ffma2(x0,wA.y,acc[0][1]);
            acc[0][2]=ffma2(x0,wB.x,acc[0][2]); acc[0][3]=ffma2(x0,wB.y,acc[0][3]);
            acc[1][0]=ffma2(x1,wA.x,acc[1][0]); acc[1][1]=ffma2(x1,wA.y,acc[1][1]);
            acc[1][2]=ffma2(x1,wB.x,acc[1][2]); acc[1][3]=ffma2(x1,wB.y,acc[1][3]);
            acc[2][0]=ffma2(x2,wA.x,acc[2][0]); acc[2][1]=ffma2(x2,wA.y,acc[2][1]);
            acc[2][2]=ffma2(x2,wB.x,acc[2][2]); acc[2][3]=ffma2(x2,wB.y,acc[2][3]);
            acc[3][0]=ffma2(x3,wA.x,acc[3][0]); acc[3][1]=ffma2(x3,wA.y,acc[3][1]);
            acc[3][2]=ffma2(x3,wB.x,acc[3][2]); acc[3][3]=ffma2(x3,wB.y,acc[3][3]);
            acc[4][0]=ffma2(x4,wA.x,acc[4][0]); acc[4][1]=ffma2(x4,wA.y,acc[4][1]);
            acc[4][2]=ffma2(x4,wB.x,acc[4][2]); acc[4][3]=ffma2(x4,wB.y,acc[4][3]);
            acc[5][0]=ffma2(x5,wA.x,acc[5][0]); acc[5][1]=ffma2(x5,wA.y,acc[5][1]);
            acc[5][2]=ffma2(x5,wB.x,acc[5][2]); acc[5][3]=ffma2(x5,wB.y,acc[5][3]);
            acc[6][0]=ffma2(x6,wA.x,acc[6][0]); acc[6][1]=ffma2(x6,wA.y,acc[6][1]);
            acc[6][2]=ffma2(x6,wB.x,acc[6][2]); acc[6][3]=ffma2(x6,wB.y,acc[6][3]);
            acc[7][0]=ffma2(x7,wA.x,acc[7][0]); acc[7][1]=ffma2(x7,wA.y,acc[7][1]);
            acc[7][2]=ffma2(x7,wB.x,acc[7][2]); acc[7][3]=ffma2(x7,wB.y,acc[7][3]);
        }
        __syncthreads();
    }

    // epilogue: bias + ssp, write feature-major (column pairs at a time)
    #pragma unroll
    for (int cp = 0; cp < 4; ++cp) {
        int c = c0 + cp * 2;
        float b0 = Bg[c], b1 = Bg[c + 1];
        float v0[8], v1[8];
        #pragma unroll
        for (int rr = 0; rr < 8; ++rr) {
            float lo, hi; unpack2(acc[rr][cp], lo, hi);
            v0[rr] = sspf(lo + b0);
            v1[rr] = sspf(hi + b1);
        }
        *reinterpret_cast<float4*>(&Xout[c * XS + r0])           = make_float4(v0[0],v0[1],v0[2],v0[3]);
        *reinterpret_cast<float4*>(&Xout[c * XS + r0 + 4])       = make_float4(v0[4],v0[5],v0[6],v0[7]);
        *reinterpret_cast<float4*>(&Xout[(c + 1) * XS + r0])     = make_float4(v1[0],v1[1],v1[2],v1[3]);
        *reinterpret_cast<float4*>(&Xout[(c + 1) * XS + r0 + 4]) = make_float4(v1[4],v1[5],v1[6],v1[7]);
    }
    __syncthreads();
}

// ---------------- main fused kernel ----------------
// dyn smem layout (floats): Xs[128*132] | Ys[128*132] | Ws[32*132] | sWf[256] | sIdx[128] | sEr[128] | sFc[128]
#define SMEM_FLOATS (16896 + 16896 + 4224 + 256 + 128 + 128 + 128)
#define SMEM_BYTES  (SMEM_FLOATS * 4)

__global__ void __launch_bounds__(NTHR, 1)
pairnet_main(const float* __restrict__ R,
             const int*   __restrict__ idx_i,
             const int*   __restrict__ idx_j,
             const float* __restrict__ iW, const float* __restrict__ iB,
             const float* __restrict__ oW, const float* __restrict__ oB,
             const float* __restrict__ oWf, const float* __restrict__ oBf,
             float* __restrict__ outRij)
{
    extern __shared__ float smem[];
    float* Xs  = smem;
    float* Ysb = Xs  + 16896;
    float* Ws  = Ysb + 16896;
    float* sWf = Ws  + 4224;
    int*   sIdx = reinterpret_cast<int*>(sWf + 256);
    float* sEr  = reinterpret_cast<float*>(sIdx + 128);
    float* sFc  = sEr + 128;

    const int tid = threadIdx.x;
    const int p0  = blockIdx.x * TILE;

    // ---- stage 1: distances, cutoff, rij output ----
    if (tid < TILE) {
        int p = p0 + tid;
        float er = 0.0f, fc = 0.0f; int ii = 0;
        if (p < NP) {
            ii = idx_i[p];
            int jj = idx_j[p];
            float dx = R[3*jj+0] - R[3*ii+0];
            float dy = R[3*jj+1] - R[3*ii+1];
            float dz = R[3*jj+2] - R[3*ii+2];
            float rij = sqrtf(dx*dx + dy*dy + dz*dz + 1e-12f);
            outRij[p] = rij;
            if (rij < 10.0f) {
                float xq = rij * 0.1f;
                float x2 = xq*xq, x3 = x2*xq, x4 = x2*x2, x5 = x4*xq;
                fc = 1.0f - 6.0f*x5 + 15.0f*x4 - 10.0f*x3;
            }
            er = expf(-rij);
        }
        sIdx[tid] = ii; sEr[tid] = er; sFc[tid] = fc;
    }
    __syncthreads();

    // ---- stage 2: radial basis into Xs (feature-major) ----
    {
        const float MU0    = 4.5399929762484854e-05f;
        const float MUSTEP = 7.8736582670224e-03f;     // (1-exp(-10))/127
        const float WIDTH  = 4096.37195f;              // ((2/128)*(1-exp(-10)))^-2
        int rr = tid & 127, half = tid >> 7;
        float er = sEr[rr], fc = sFc[rr];
        int k0 = half * 64;
        #pragma unroll 8
        for (int k = k0; k < k0 + 64; ++k) {
            float mu = MU0 + (float)k * MUSTEP;
            float d  = er - mu;
            Xs[k * XS + rr] = fc * __expf(-WIDTH * d * d);
        }
    }
    __syncthreads();

    // ---- stage 3: 5 blocks of fused MLPs ----
    for (int b = 0; b < NBLK; ++b) {
        // interaction: x = ssp(x@iW + iB), twice, in place
        for (int l = 0; l < 2; ++l)
            gemm128_ssp(iW + (size_t)(b*2 + l) * HH * HH, iB + (b*2 + l) * HH,
                        Xs, Xs, Ws, tid);
        // output chain: y = ssp(y@oW + oB), twice, into Ysb
        for (int l = 0; l < 2; ++l)
            gemm128_ssp(oW + (size_t)(b*2 + l) * HH * HH, oB + (b*2 + l) * HH,
                        (l == 0) ? Xs : Ysb, Ysb, Ws, tid);

        // head: out_e = y @ oWf[b] + oBf[b]   (128x2), then segment-atomic
        sWf[tid] = oWf[b * 256 + tid];
        __syncthreads();
        {
            int r = tid >> 1, o = tid & 1;
            float a = 0.0f;
            #pragma unroll 8
            for (int k = 0; k < HH; ++k)
                a += Ysb[k * XS + r] * sWf[2 * k + o];
            a += oBf[b * 2 + o];
            if (p0 + r < NP)
                atomicAdd(&g_blockout[(b * NATOMS + sIdx[r]) * 2 + o], a);
        }
        __syncthreads();
    }
}

// ---------------- zero scratch ----------------
__global__ void zero_scratch() {
    int i = blockIdx.x * blockDim.x + threadIdx.x;
    if (i < NBLK * NATOMS * 2) g_blockout[i] = 0.0f;
    if (i == 0) g_nh = 0.0f;
}

// ---------------- finalize: scale/shift + nhloss ----------------
__global__ void finalize_kernel(const int* __restrict__ Z,
                                const float* __restrict__ scales,
                                const float* __restrict__ shifts,
                                float* __restrict__ out)
{
    int a = blockIdx.x * blockDim.x + threadIdx.x;
    float local = 0.0f;
    if (a < NATOMS) {
        int z = Z[a];
        #pragma unroll
        for (int o = 0; o < 2; ++o) {
            float tot = 0.0f, last2 = 0.0f;
            #pragma unroll
            for (int b = 0; b < NBLK; ++b) {
                float v = g_blockout[(b * NATOMS + a) * 2 + o];
                tot += v;
                float v2 = v * v;
                if (b > 0) local += v2 / (v2 + last2 + 1e-7f);
                last2 = v2;
            }
            out[a * 2 + o] = tot * scales[o * 95 + z] + shifts[o * 95 + z];
        }
    }
    __shared__ float red[256];
    red[threadIdx.x] = local;
    __syncthreads();
    #pragma unroll
    for (int s = 128; s > 0; s >>= 1) {
        if (threadIdx.x < s) red[threadIdx.x] += red[threadIdx.x + s];
        __syncthreads();
    }
    if (threadIdx.x == 0) atomicAdd(&g_nh, red[0]);
}

__global__ void write_nh(float* __restrict__ out) {
    out[NATOMS * 2 + NP] = g_nh * (1.0f / 20000.0f);   // mean over [N, NO]
}

// ---------------- launch ----------------
extern "C" void kernel_launch(void* const* d_in, const int* in_sizes, int n_in,
                              void* d_out, int out_size)
{
    const int*   Z      = (const int*)  d_in[0];
    const float* R      = (const float*)d_in[1];
    const int*   idx_i  = (const int*)  d_in[2];
    const int*   idx_j  = (const int*)  d_in[3];
    const float* iW     = (const float*)d_in[4];
    const float* iB     = (const float*)d_in[5];
    const float* oW     = (const float*)d_in[6];
    const float* oB     = (const float*)d_in[7];
    const float* oWf    = (const float*)d_in[8];
    const float* oBf    = (const float*)d_in[9];
    const float* scales = (const float*)d_in[10];
    const float* shifts = (const float*)d_in[11];
    float* out = (float*)d_out;

    cudaFuncSetAttribute(pairnet_main,
                         cudaFuncAttributeMaxDynamicSharedMemorySize, SMEM_BYTES);

    zero_scratch<<<(NBLK * NATOMS * 2 + 255) / 256, 256>>>();

    int nblocks = (NP + TILE - 1) / TILE;   // 1954
    pairnet_main<<<nblocks, NTHR, SMEM_BYTES>>>(
        R, idx_i, idx_j, iW, iB, oW, oB, oWf, oBf, out + 2 * NATOMS);

    finalize_kernel<<<(NATOMS + 255) / 256, 256>>>(Z, scales, shifts, out);
    write_nh<<<1, 1>>>(out);
}

// round 2
// speedup vs baseline: 1.0002x; 1.0002x over previous
#include <cuda_runtime.h>

typedef unsigned long long ull;

#define NP      250000
#define NATOMS  10000
#define HH      128
#define NBLK    5
#define TILE    128
#define NTHR    256
#define XS      132            // padded row stride for [feat][row] smem tiles

// ---------------- device scratch (no allocation allowed) ----------------
__device__ float g_blockout[NBLK * NATOMS * 2];   // per-block segment sums
__device__ float g_nh;                            // nhloss accumulator

// ---------------- helpers ----------------
__device__ __forceinline__ ull pack2(float x) {
    ull d; asm("mov.b64 %0, {%1, %1};" : "=l"(d) : "f"(x)); return d;
}
__device__ __forceinline__ ull ffma2(ull a, ull b, ull c) {
    ull d; asm("fma.rn.f32x2 %0, %1, %2, %3;" : "=l"(d) : "l"(a), "l"(b), "l"(c)); return d;
}
__device__ __forceinline__ void unpack2(ull v, float& lo, float& hi) {
    asm("mov.b64 {%0, %1}, %2;" : "=f"(lo), "=f"(hi) : "l"(v));
}
// shifted softplus: softplus(x) - ln2, numerically stable, fast intrinsics
// (abs error ~3e-7, fine for 1e-3 tolerance)
__device__ __forceinline__ float sspf(float x) {
    float e = __expf(-fabsf(x));
    return fmaxf(x, 0.0f) + __logf(1.0f + e) - 0.69314718055994531f;
}

// ---------------- 128x128x128 fused GEMM + bias + ssp ----------------
// Xin/Xout are feature-major smem tiles: X[k*XS + r]. Safe for Xin==Xout.
// W global row-major [k][c]; panel-staged through Ws smem.
__device__ __noinline__ void gemm128_ssp(
    const float* __restrict__ Wg, const float* __restrict__ Bg,
    const float* Xin, float* Xout, float* Ws, int tid)
{
    const int tx = tid & 15, ty = tid >> 4;
    const int c0 = tx * 8, r0 = ty * 8;

    ull acc[8][4];
    #pragma unroll
    for (int i = 0; i < 8; ++i)
        #pragma unroll
        for (int j = 0; j < 4; ++j) acc[i][j] = 0ull;

    #pragma unroll 1
    for (int kp = 0; kp < 4; ++kp) {
        // stage 32-row W panel into smem
        const float4* Wg4 = reinterpret_cast<const float4*>(Wg + kp * 32 * HH);
        #pragma unroll
        for (int j = 0; j < 4; ++j) {
            int t  = tid + j * NTHR;       // 0..1023
            int i  = t >> 5;               // panel row 0..31
            int c4 = t & 31;               // float4 column
            float4 v = Wg4[i * 32 + c4];
            *reinterpret_cast<float4*>(&Ws[i * XS + c4 * 4]) = v;
        }
        __syncthreads();

        #pragma unroll
        for (int kk = 0; kk < 32; ++kk) {
            const float* xr = &Xin[(kp * 32 + kk) * XS + r0];
            float4 xa = *reinterpret_cast<const float4*>(xr);
            float4 xb = *reinterpret_cast<const float4*>(xr + 4);
            const ulonglong2* wr =
                reinterpret_cast<const ulonglong2*>(&Ws[kk * XS + c0]);
            ulonglong2 wA = wr[0];   // cols c0..c0+3 as two f32x2
            ulonglong2 wB = wr[1];   // cols c0+4..c0+7

            ull x0 = pack2(xa.x), x1 = pack2(xa.y), x2 = pack2(xa.z), x3 = pack2(xa.w);
            ull x4 = pack2(xb.x), x5 = pack2(xb.y), x6 = pack2(xb.z), x7 = pack2(xb.w);

            acc[0][0]=ffma2(x0,wA.x,acc[0][0]); acc[0][1]=ffma2(x0,wA.y,acc[0][1]);
            acc[0][2]=ffma2(x0,wB.x,acc[0][2]); acc[0][3]=ffma2(x0,wB.y,acc[0][3]);
            acc[1][0]=ffma2(x1,wA.x,acc[1][0]); acc[1][1]=ffma2(x1,wA.y,acc[1][1]);
            acc[1][2]=ffma2(x1,wB.x,acc[1][2]); acc[1][3]=ffma2(x1,wB.y,acc[1][3]);
            acc[2][0]=ffma2(x2,wA.x,acc[2][0]); acc[2][1]=ffma2(x2,wA.y,acc[2][1]);
            acc[2][2]=ffma2(x2,wB.x,acc[2][2]); acc[2][3]=ffma2(x2,wB.y,acc[2][3]);
            acc[3][0]=ffma2(x3,wA.x,acc[3][0]); acc[3][1]=ffma2(x3,wA.y,acc[3][1]);
            acc[3][2]=ffma2(x3,wB.x,acc[3][2]); acc[3][3]=ffma2(x3,wB.y,acc[3][3]);
            acc[4][0]=ffma2(x4,wA.x,acc[4][0]); acc[4][1]=ffma2(x4,wA.y,acc[4][1]);
            acc[4][2]=ffma2(x4,wB.x,acc[4][2]); acc[4][3]=ffma2(x4,wB.y,acc[4][3]);
            acc[5][0]=ffma2(x5,wA.x,acc[5][0]); acc[5][1]=ffma2(x5,wA.y,acc[5][1]);
            acc[5][2]=ffma2(x5,wB.x,acc[5][2]); acc[5][3]=ffma2(x5,wB.y,acc[5][3]);
            acc[6][0]=ffma2(x6,wA.x,acc[6][0]); acc[6][1]=ffma2(x6,wA.y,acc[6][1]);
            acc[6][2]=ffma2(x6,wB.x,acc[6][2]); acc[6][3]=ffma2(x6,wB.y,acc[6][3]);
            acc[7][0]=ffma2(x7,wA.x,acc[7][0]); acc[7][1]=ffma2(x7,wA.y,acc[7][1]);
            acc[7][2]=ffma2(x7,wB.x,acc[7][2]); acc[7][3]=ffma2(x7,wB.y,acc[7][3]);
        }
        __syncthreads();
    }

    // epilogue: bias + ssp, write feature-major (column pairs at a time)
    #pragma unroll
    for (int cp = 0; cp < 4; ++cp) {
        int c = c0 + cp * 2;
        float b0 = Bg[c], b1 = Bg[c + 1];
        float v0[8], v1[8];
        #pragma unroll
        for (int rr = 0; rr < 8; ++rr) {
            float lo, hi; unpack2(acc[rr][cp], lo, hi);
            v0[rr] = sspf(lo + b0);
            v1[rr] = sspf(hi + b1);
        }
        *reinterpret_cast<float4*>(&Xout[c * XS + r0])           = make_float4(v0[0],v0[1],v0[2],v0[3]);
        *reinterpret_cast<float4*>(&Xout[c * XS + r0 + 4])       = make_float4(v0[4],v0[5],v0[6],v0[7]);
        *reinterpret_cast<float4*>(&Xout[(c + 1) * XS + r0])     = make_float4(v1[0],v1[1],v1[2],v1[3]);
        *reinterpret_cast<float4*>(&Xout[(c + 1) * XS + r0 + 4]) = make_float4(v1[4],v1[5],v1[6],v1[7]);
    }
    __syncthreads();
}

// ---------------- main fused kernel ----------------
// dyn smem layout (floats): Xs[128*132] | Ys[128*132] | Ws[32*132] | sWf[256] | sIdx[128] | sEr[128] | sFc[128]
#define SMEM_FLOATS (16896 + 16896 + 4224 + 256 + 128 + 128 + 128)
#define SMEM_BYTES  (SMEM_FLOATS * 4)

__global__ void __launch_bounds__(NTHR, 1)
pairnet_main(const float* __restrict__ R,
             const int*   __restrict__ idx_i,
             const int*   __restrict__ idx_j,
             const float* __restrict__ iW, const float* __restrict__ iB,
             const float* __restrict__ oW, const float* __restrict__ oB,
             const float* __restrict__ oWf, const float* __restrict__ oBf,
             float* __restrict__ outRij)
{
    extern __shared__ float smem[];
    float* Xs  = smem;
    float* Ysb = Xs  + 16896;
    float* Ws  = Ysb + 16896;
    float* sWf = Ws  + 4224;
    int*   sIdx = reinterpret_cast<int*>(sWf + 256);
    float* sEr  = reinterpret_cast<float*>(sIdx + 128);
    float* sFc  = sEr + 128;

    const int tid = threadIdx.x;
    const int p0  = blockIdx.x * TILE;

    // ---- stage 1: distances, cutoff, rij output ----
    if (tid < TILE) {
        int p = p0 + tid;
        float er = 0.0f, fc = 0.0f; int ii = 0;
        if (p < NP) {
            ii = idx_i[p];
            int jj = idx_j[p];
            float dx = R[3*jj+0] - R[3*ii+0];
            float dy = R[3*jj+1] - R[3*ii+1];
            float dz = R[3*jj+2] - R[3*ii+2];
            float rij = sqrtf(dx*dx + dy*dy + dz*dz + 1e-12f);
            outRij[p] = rij;
            if (rij < 10.0f) {
                float xq = rij * 0.1f;
                float x2 = xq*xq, x3 = x2*xq, x4 = x2*x2, x5 = x4*xq;
                fc = 1.0f - 6.0f*x5 + 15.0f*x4 - 10.0f*x3;
            }
            er = expf(-rij);
        }
        sIdx[tid] = ii; sEr[tid] = er; sFc[tid] = fc;
    }
    __syncthreads();

    // ---- stage 2: radial basis into Xs (feature-major) ----
    {
        const float MU0    = 4.5399929762484854e-05f;
        const float MUSTEP = 7.8736582670224e-03f;     // (1-exp(-10))/127
        const float WIDTH  = 4096.37195f;              // ((2/128)*(1-exp(-10)))^-2
        int rr = tid & 127, half = tid >> 7;
        float er = sEr[rr], fc = sFc[rr];
        int k0 = half * 64;
        #pragma unroll 8
        for (int k = k0; k < k0 + 64; ++k) {
            float mu = MU0 + (float)k * MUSTEP;
            float d  = er - mu;
            Xs[k * XS + rr] = fc * __expf(-WIDTH * d * d);
        }
    }
    __syncthreads();

    // ---- stage 3: 5 blocks of fused MLPs ----
    for (int b = 0; b < NBLK; ++b) {
        // interaction: x = ssp(x@iW + iB), twice, in place
        for (int l = 0; l < 2; ++l)
            gemm128_ssp(iW + (size_t)(b*2 + l) * HH * HH, iB + (b*2 + l) * HH,
                        Xs, Xs, Ws, tid);
        // output chain: y = ssp(y@oW + oB), twice, into Ysb
        for (int l = 0; l < 2; ++l)
            gemm128_ssp(oW + (size_t)(b*2 + l) * HH * HH, oB + (b*2 + l) * HH,
                        (l == 0) ? Xs : Ysb, Ysb, Ws, tid);

        // head: out_e = y @ oWf[b] + oBf[b]   (128x2), then segment-atomic
        sWf[tid] = oWf[b * 256 + tid];
        __syncthreads();
        {
            int r = tid >> 1, o = tid & 1;
            float a = 0.0f;
            #pragma unroll 8
            for (int k = 0; k < HH; ++k)
                a += Ysb[k * XS + r] * sWf[2 * k + o];
            a += oBf[b * 2 + o];
            if (p0 + r < NP)
                atomicAdd(&g_blockout[(b * NATOMS + sIdx[r]) * 2 + o], a);
        }
        __syncthreads();
    }
}

// ---------------- zero scratch ----------------
__global__ void zero_scratch() {
    int i = blockIdx.x * blockDim.x + threadIdx.x;
    if (i < NBLK * NATOMS * 2) g_blockout[i] = 0.0f;
    if (i == 0) g_nh = 0.0f;
}

// ---------------- finalize: scale/shift + nhloss ----------------
__global__ void finalize_kernel(const int* __restrict__ Z,
                                const float* __restrict__ scales,
                                const float* __restrict__ shifts,
                                float* __restrict__ out)
{
    int a = blockIdx.x * blockDim.x + threadIdx.x;
    float local = 0.0f;
    if (a < NATOMS) {
        int z = Z[a];
        #pragma unroll
        for (int o = 0; o < 2; ++o) {
            float tot = 0.0f, last2 = 0.0f;
            #pragma unroll
            for (int b = 0; b < NBLK; ++b) {
                float v = g_blockout[(b * NATOMS + a) * 2 + o];
                tot += v;
                float v2 = v * v;
                if (b > 0) local += v2 / (v2 + last2 + 1e-7f);
                last2 = v2;
            }
            out[a * 2 + o] = tot * scales[o * 95 + z] + shifts[o * 95 + z];
        }
    }
    __shared__ float red[256];
    red[threadIdx.x] = local;
    __syncthreads();
    #pragma unroll
    for (int s = 128; s > 0; s >>= 1) {
        if (threadIdx.x < s) red[threadIdx.x] += red[threadIdx.x + s];
        __syncthreads();
    }
    if (threadIdx.x == 0) atomicAdd(&g_nh, red[0]);
}

__global__ void write_nh(float* __restrict__ out) {
    out[NATOMS * 2 + NP] = g_nh * (1.0f / 20000.0f);   // mean over [N, NO]
}

// ---------------- launch ----------------
extern "C" void kernel_launch(void* const* d_in, const int* in_sizes, int n_in,
                              void* d_out, int out_size)
{
    const int*   Z      = (const int*)  d_in[0];
    const float* R      = (const float*)d_in[1];
    const int*   idx_i  = (const int*)  d_in[2];
    const int*   idx_j  = (const int*)  d_in[3];
    const float* iW     = (const float*)d_in[4];
    const float* iB     = (const float*)d_in[5];
    const float* oW     = (const float*)d_in[6];
    const float* oB     = (const float*)d_in[7];
    const float* oWf    = (const float*)d_in[8];
    const float* oBf    = (const float*)d_in[9];
    const float* scales = (const float*)d_in[10];
    const float* shifts = (const float*)d_in[11];
    float* out = (float*)d_out;

    cudaFuncSetAttribute(pairnet_main,
                         cudaFuncAttributeMaxDynamicSharedMemorySize, SMEM_BYTES);

    zero_scratch<<<(NBLK * NATOMS * 2 + 255) / 256, 256>>>();

    int nblocks = (NP + TILE - 1) / TILE;   // 1954
    pairnet_main<<<nblocks, NTHR, SMEM_BYTES>>>(
        R, idx_i, idx_j, iW, iB, oW, oB, oWf, oBf, out + 2 * NATOMS);

    finalize_kernel<<<(NATOMS + 255) / 256, 256>>>(Z, scales, shifts, out);
    write_nh<<<1, 1>>>(out);
}

// round 4
// speedup vs baseline: 1.7116x; 1.7113x over previous
#include <cuda_runtime.h>
#include <cuda_bf16.h>
#include <cstdint>

#define NP      250000
#define NATOMS  10000
#define NBLK    5
#define NLAYERS 20
#define NTHR    256

// smem layout (bytes)
#define BUF0_OFF   0
#define BUF1_OFF   49152
#define SPILL_OFF  98304
#define BIAS_OFF   196608
#define WF_OFF     197120
#define ER_OFF     198144
#define FC_OFF     198656
#define IDX_OFF    199168
#define SMEM_BYTES 199680

__device__ float g_blockout[NBLK * NATOMS * 2];
__device__ float g_nh;
// pre-split, pre-swizzled weights: [L][limb][k][swizzled n]  (20*3*16384 bf16)
__device__ __align__(16) __nv_bfloat16 g_Wb[NLAYERS * 3 * 16384];

// ---------------- helpers ----------------
__device__ __forceinline__ uint32_t smem_u32(const void* p) {
    uint32_t a;
    asm("{ .reg .u64 t; cvta.to.shared.u64 t, %1; cvt.u32.u64 %0, t; }" : "=r"(a) : "l"(p));
    return a;
}
__device__ __forceinline__ void mma_bf16(float* c, uint32_t a0, uint32_t a1, uint32_t a2, uint32_t a3,
                                         uint32_t b0, uint32_t b1) {
    asm volatile("mma.sync.aligned.m16n8k16.row.col.f32.bf16.bf16.f32 "
                 "{%0,%1,%2,%3}, {%4,%5,%6,%7}, {%8,%9}, {%0,%1,%2,%3};"
                 : "+f"(c[0]), "+f"(c[1]), "+f"(c[2]), "+f"(c[3])
                 : "r"(a0), "r"(a1), "r"(a2), "r"(a3), "r"(b0), "r"(b1));
}
__device__ __forceinline__ void ldsm4t(uint32_t addr, uint32_t& r0, uint32_t& r1, uint32_t& r2, uint32_t& r3) {
    asm volatile("ldmatrix.sync.aligned.m8n8.x4.trans.shared.b16 {%0,%1,%2,%3}, [%4];"
                 : "=r"(r0), "=r"(r1), "=r"(r2), "=r"(r3) : "r"(addr));
}
#define CP_ASYNC(dst, src) asm volatile("cp.async.cg.shared.global [%0], [%1], 16;" :: "r"(dst), "l"(src) : "memory")
#define CP_COMMIT()        asm volatile("cp.async.commit_group;" ::: "memory")
#define CP_WAIT(n)         asm volatile("cp.async.wait_group %0;" :: "n"(n) : "memory")

__device__ __forceinline__ float sspf(float x) {
    float e = __expf(-fabsf(x));
    return fmaxf(x, 0.0f) + __logf(1.0f + e) - 0.69314718055994531f;
}
// exact 3-limb split via bf16 truncation
__device__ __forceinline__ void split3u(float v, uint32_t& u0, uint32_t& u1, uint32_t& u2) {
    u0 = __float_as_uint(v) & 0xFFFF0000u;
    float r = v - __uint_as_float(u0);
    u1 = __float_as_uint(r) & 0xFFFF0000u;
    float r2 = r - __uint_as_float(u1);
    u2 = __float_as_uint(r2) & 0xFFFF0000u;
}
// pack high-16s of (a, b) -> bf16x2 {a, b}
__device__ __forceinline__ uint32_t packhi(uint32_t a, uint32_t b) {
    return __byte_perm(a, b, 0x7632);
}

// ---------------- weight prep: split + transpose-free swizzle ----------------
__global__ void split_weights(const float* __restrict__ iW, const float* __restrict__ oW) {
    int L = blockIdx.x, sl = blockIdx.y;
    int b = L >> 2, l = L & 3;
    const float* W = (l < 2) ? iW + (size_t)(b * 2 + l) * 16384
                             : oW + (size_t)(b * 2 + l - 2) * 16384;
    size_t base = (size_t)L * 3 * 16384;
    for (int e = sl * 2048 + threadIdx.x; e < (sl + 1) * 2048; e += 256) {
        int k = e >> 7, n = e & 127;
        uint32_t u0, u1, u2;
        split3u(W[e], u0, u1, u2);
        int c = (n >> 3) ^ (k & 15);
        int idx = k * 128 + c * 8 + (n & 7);
        __nv_bfloat16_raw r0; r0.x = (unsigned short)(u0 >> 16);
        __nv_bfloat16_raw r1; r1.x = (unsigned short)(u1 >> 16);
        __nv_bfloat16_raw r2; r2.x = (unsigned short)(u2 >> 16);
        g_Wb[base + idx]             = __nv_bfloat16(r0);
        g_Wb[base + 16384 + idx]     = __nv_bfloat16(r1);
        g_Wb[base + 32768 + idx]     = __nv_bfloat16(r2);
    }
}

// ---------------- MMA phase: 4 K-chunks against one 48KB B half ----------------
struct LaneCtx { uint32_t sb; int lane_row; int lane_cadd; };

__device__ __forceinline__ void do_phase(int qbase, uint32_t bufoff,
                                         const uint32_t* A, float* C, const LaneCtx& lc) {
    const int IA[6] = {0, 1, 0, 2, 1, 0};
    const int IB[6] = {0, 0, 1, 0, 1, 2};
    #pragma unroll
    for (int qq = 0; qq < 4; ++qq) {
        uint32_t rowaddr = lc.sb + bufoff + (uint32_t)(qq * 16 + lc.lane_row) * 256u;
        #pragma unroll
        for (int jq = 0; jq < 4; ++jq) {
            uint32_t Bf[2][3][4];
            #pragma unroll
            for (int jp = 0; jp < 2; ++jp) {
                int c  = 2 * (2 * jq + jp) + lc.lane_cadd;
                int cp = c ^ lc.lane_row;
                uint32_t addr = rowaddr + (uint32_t)cp * 16u;
                #pragma unroll
                for (int t = 0; t < 3; ++t)
                    ldsm4t(addr + (uint32_t)t * 16384u,
                           Bf[jp][t][0], Bf[jp][t][1], Bf[jp][t][2], Bf[jp][t][3]);
            }
            const uint32_t* Aq = A + (qbase + qq) * 12;
            #pragma unroll
            for (int s = 0; s < 6; ++s) {
                const uint32_t* Aa = Aq + IA[s] * 4;
                #pragma unroll
                for (int cc = 0; cc < 4; ++cc) {
                    int jp = cc >> 1, hf = cc & 1;
                    mma_bf16(&C[(4 * jq + cc) * 4], Aa[0], Aa[1], Aa[2], Aa[3],
                             Bf[jp][IB[s]][hf * 2], Bf[jp][IB[s]][hf * 2 + 1]);
                }
            }
        }
    }
}

// ---------------- main kernel ----------------
__global__ void __launch_bounds__(NTHR, 1)
pairnet_mma(const float* __restrict__ R,
            const int*   __restrict__ idx_i,
            const int*   __restrict__ idx_j,
            const float* __restrict__ iB, const float* __restrict__ oB,
            const float* __restrict__ oWf, const float* __restrict__ oBf,
            float* __restrict__ outRij)
{
    extern __shared__ char smem[];
    uint32_t sb = smem_u32(smem);
    float* sBias = (float*)(smem + BIAS_OFF);
    float* sWf   = (float*)(smem + WF_OFF);
    float* sEr   = (float*)(smem + ER_OFF);
    float* sFc   = (float*)(smem + FC_OFF);
    int*   sIdx  = (int*)  (smem + IDX_OFF);
    uint4* sSpill = (uint4*)(smem + SPILL_OFF);

    const int tid = threadIdx.x;
    const int w = tid >> 5, l = tid & 31;
    const int g = l >> 2, four = l & 3;
    const int p0 = blockIdx.x * 128;
    LaneCtx lc; lc.sb = sb; lc.lane_row = l & 15; lc.lane_cadd = l >> 4;

    // issue copies for layer 0 (both halves)
    {
        const char* gsrc = (const char*)g_Wb;
        #pragma unroll
        for (int h = 0; h < 2; ++h) {
            #pragma unroll
            for (int t = 0; t < 3; ++t)
                #pragma unroll
                for (int i = 0; i < 4; ++i) {
                    int idx = i * 256 + tid;
                    CP_ASYNC(sb + (uint32_t)(h * 49152 + t * 16384 + idx * 16),
                             gsrc + t * 32768 + h * 16384 + idx * 16);
                }
            CP_COMMIT();
        }
    }

    // geometry
    if (tid < 128) {
        int p = p0 + tid;
        float er = 0.0f, fc = 0.0f; int ii = 0;
        if (p < NP) {
            ii = idx_i[p];
            int jj = idx_j[p];
            float dx = R[3*jj+0] - R[3*ii+0];
            float dy = R[3*jj+1] - R[3*ii+1];
            float dz = R[3*jj+2] - R[3*ii+2];
            float rij = sqrtf(dx*dx + dy*dy + dz*dz + 1e-12f);
            outRij[p] = rij;
            if (rij < 10.0f) {
                float xq = rij * 0.1f;
                float x2 = xq*xq, x3 = x2*xq, x4 = x2*x2, x5 = x4*xq;
                fc = 1.0f - 6.0f*x5 + 15.0f*x4 - 10.0f*x3;
            }
            er = expf(-rij);
        }
        sIdx[tid] = ii; sEr[tid] = er; sFc[tid] = fc;
    }
    __syncthreads();

    // basis -> A fragments (registers)
    uint32_t A[96];
    {
        const float MU0    = 4.5399929762484854e-05f;
        const float MUSTEP = 7.8736582670224e-03f;
        const float WIDTH  = 4096.37195f;
        float er0 = sEr[16*w + g],     fc0 = sFc[16*w + g];
        float er8 = sEr[16*w + g + 8], fc8 = sFc[16*w + g + 8];
        #pragma unroll
        for (int q = 0; q < 8; ++q) {
            #pragma unroll
            for (int jj = 0; jj < 2; ++jj) {
                int k0 = 16*q + 8*jj + 2*four;
                float m0 = MU0 + (float)k0 * MUSTEP;
                float m1 = MU0 + (float)(k0+1) * MUSTEP;
                float d;
                d = er0 - m0; float e0 = fc0 * __expf(-WIDTH * d * d);
                d = er0 - m1; float e1 = fc0 * __expf(-WIDTH * d * d);
                d = er8 - m0; float e2 = fc8 * __expf(-WIDTH * d * d);
                d = er8 - m1; float e3 = fc8 * __expf(-WIDTH * d * d);
                uint32_t u[4][3];
                split3u(e0, u[0][0], u[0][1], u[0][2]);
                split3u(e1, u[1][0], u[1][1], u[1][2]);
                split3u(e2, u[2][0], u[2][1], u[2][2]);
                split3u(e3, u[3][0], u[3][1], u[3][2]);
                #pragma unroll
                for (int t = 0; t < 3; ++t) {
                    A[q*12 + t*4 + jj*2 + 0] = packhi(u[0][t], u[1][t]);
                    A[q*12 + t*4 + jj*2 + 1] = packhi(u[2][t], u[3][t]);
                }
            }
        }
    }

    float C[64];

    #pragma unroll 1
    for (int L = 0; L < NLAYERS; ++L) {
        const int b = L >> 2, lay = L & 3;
        // stage bias (+ head weights)
        const float* bp = (lay < 2) ? iB + (b*2 + lay)*128 : oB + (b*2 + lay - 2)*128;
        if (tid < 128) sBias[tid] = bp[tid];
        if (lay == 3) sWf[tid] = oWf[b*256 + tid];

        #pragma unroll
        for (int i = 0; i < 64; ++i) C[i] = 0.0f;

        CP_WAIT(1);
        __syncthreads();
        do_phase(0, BUF0_OFF, A, C, lc);

        CP_WAIT(0);
        __syncthreads();
        if (L < NLAYERS - 1) {   // prefetch next layer's half 0
            const char* gsrc = (const char*)g_Wb + (size_t)(L + 1) * 98304;
            #pragma unroll
            for (int t = 0; t < 3; ++t)
                #pragma unroll
                for (int i = 0; i < 4; ++i) {
                    int idx = i * 256 + tid;
                    CP_ASYNC(sb + (uint32_t)(t * 16384 + idx * 16),
                             gsrc + t * 32768 + idx * 16);
                }
            CP_COMMIT();
        }
        do_phase(4, BUF1_OFF, A, C, lc);

        if (lay == 2) {   // spill x before overwriting A with y
            #pragma unroll
            for (int i = 0; i < 24; ++i) sSpill[i * 256 + tid] = ((uint4*)A)[i];
        }

        if (lay < 3) {
            // epilogue: bias + ssp + split -> new A frags
            #pragma unroll
            for (int q = 0; q < 8; ++q) {
                #pragma unroll
                for (int jj = 0; jj < 2; ++jj) {
                    int j = 2*q + jj;
                    float2 bb = *(const float2*)&sBias[j*8 + four*2];
                    float e0 = sspf(C[j*4+0] + bb.x);
                    float e1 = sspf(C[j*4+1] + bb.y);
                    float e2 = sspf(C[j*4+2] + bb.x);
                    float e3 = sspf(C[j*4+3] + bb.y);
                    uint32_t u[4][3];
                    split3u(e0, u[0][0], u[0][1], u[0][2]);
                    split3u(e1, u[1][0], u[1][1], u[1][2]);
                    split3u(e2, u[2][0], u[2][1], u[2][2]);
                    split3u(e3, u[3][0], u[3][1], u[3][2]);
                    #pragma unroll
                    for (int t = 0; t < 3; ++t) {
                        A[q*12 + t*4 + jj*2 + 0] = packhi(u[0][t], u[1][t]);
                        A[q*12 + t*4 + jj*2 + 1] = packhi(u[2][t], u[3][t]);
                    }
                }
            }
        } else {
            // head: y2 = ssp(C + bias); out = y2 @ Wf + oBf; segment atomics
            float s00 = 0.f, s01 = 0.f, s10 = 0.f, s11 = 0.f;
            #pragma unroll
            for (int j = 0; j < 16; ++j) {
                int col0 = j*8 + four*2;
                float2 bb = *(const float2*)&sBias[col0];
                float e0 = sspf(C[j*4+0] + bb.x);
                float e1 = sspf(C[j*4+1] + bb.y);
                float e2 = sspf(C[j*4+2] + bb.x);
                float e3 = sspf(C[j*4+3] + bb.y);
                float2 w0 = *(const float2*)&sWf[col0*2];
                float2 w1 = *(const float2*)&sWf[col0*2 + 2];
                s00 = fmaf(e0, w0.x, fmaf(e1, w1.x, s00));
                s01 = fmaf(e0, w0.y, fmaf(e1, w1.y, s01));
                s10 = fmaf(e2, w0.x, fmaf(e3, w1.x, s10));
                s11 = fmaf(e2, w0.y, fmaf(e3, w1.y, s11));
            }
            #pragma unroll
            for (int d = 1; d <= 2; d <<= 1) {
                s00 += __shfl_xor_sync(0xffffffffu, s00, d);
                s01 += __shfl_xor_sync(0xffffffffu, s01, d);
                s10 += __shfl_xor_sync(0xffffffffu, s10, d);
                s11 += __shfl_xor_sync(0xffffffffu, s11, d);
            }
            if (four == 0) {
                float bf0 = __ldg(&oBf[b*2]), bf1 = __ldg(&oBf[b*2+1]);
                int r0 = 16*w + g, r1 = r0 + 8;
                if (p0 + r0 < NP) {
                    int a = sIdx[r0];
                    atomicAdd(&g_blockout[(b*NATOMS + a)*2 + 0], s00 + bf0);
                    atomicAdd(&g_blockout[(b*NATOMS + a)*2 + 1], s01 + bf1);
                }
                if (p0 + r1 < NP) {
                    int a = sIdx[r1];
                    atomicAdd(&g_blockout[(b*NATOMS + a)*2 + 0], s10 + bf0);
                    atomicAdd(&g_blockout[(b*NATOMS + a)*2 + 1], s11 + bf1);
                }
            }
            // restore x for next block
            if (L < NLAYERS - 1) {
                #pragma unroll
                for (int i = 0; i < 24; ++i) ((uint4*)A)[i] = sSpill[i * 256 + tid];
            }
        }

        __syncthreads();
        if (L < NLAYERS - 1) {   // prefetch next layer's half 1
            const char* gsrc = (const char*)g_Wb + (size_t)(L + 1) * 98304;
            #pragma unroll
            for (int t = 0; t < 3; ++t)
                #pragma unroll
                for (int i = 0; i < 4; ++i) {
                    int idx = i * 256 + tid;
                    CP_ASYNC(sb + (uint32_t)(49152 + t * 16384 + idx * 16),
                             gsrc + t * 32768 + 16384 + idx * 16);
                }
            CP_COMMIT();
        }
    }
}

// ---------------- zero / finalize ----------------
__global__ void zero_scratch() {
    int i = blockIdx.x * blockDim.x + threadIdx.x;
    if (i < NBLK * NATOMS * 2) g_blockout[i] = 0.0f;
    if (i == 0) g_nh = 0.0f;
}

__global__ void finalize_kernel(const int* __restrict__ Z,
                                const float* __restrict__ scales,
                                const float* __restrict__ shifts,
                                float* __restrict__ out)
{
    int a = blockIdx.x * blockDim.x + threadIdx.x;
    float local = 0.0f;
    if (a < NATOMS) {
        int z = Z[a];
        #pragma unroll
        for (int o = 0; o < 2; ++o) {
            float tot = 0.0f, last2 = 0.0f;
            #pragma unroll
            for (int b = 0; b < NBLK; ++b) {
                float v = g_blockout[(b * NATOMS + a) * 2 + o];
                tot += v;
                float v2 = v * v;
                if (b > 0) local += v2 / (v2 + last2 + 1e-7f);
                last2 = v2;
            }
            out[a * 2 + o] = tot * scales[o * 95 + z] + shifts[o * 95 + z];
        }
    }
    __shared__ float red[256];
    red[threadIdx.x] = local;
    __syncthreads();
    #pragma unroll
    for (int s = 128; s > 0; s >>= 1) {
        if (threadIdx.x < s) red[threadIdx.x] += red[threadIdx.x + s];
        __syncthreads();
    }
    if (threadIdx.x == 0) atomicAdd(&g_nh, red[0]);
}

__global__ void write_nh(float* __restrict__ out) {
    out[NATOMS * 2 + NP] = g_nh * (1.0f / 20000.0f);
}

// ---------------- launch ----------------
extern "C" void kernel_launch(void* const* d_in, const int* in_sizes, int n_in,
                              void* d_out, int out_size)
{
    const int*   Z      = (const int*)  d_in[0];
    const float* R      = (const float*)d_in[1];
    const int*   idx_i  = (const int*)  d_in[2];
    const int*   idx_j  = (const int*)  d_in[3];
    const float* iW     = (const float*)d_in[4];
    const float* iB     = (const float*)d_in[5];
    const float* oW     = (const float*)d_in[6];
    const float* oB     = (const float*)d_in[7];
    const float* oWf    = (const float*)d_in[8];
    const float* oBf    = (const float*)d_in[9];
    const float* scales = (const float*)d_in[10];
    const float* shifts = (const float*)d_in[11];
    float* out = (float*)d_out;

    cudaFuncSetAttribute(pairnet_mma,
                         cudaFuncAttributeMaxDynamicSharedMemorySize, SMEM_BYTES);

    zero_scratch<<<(NBLK * NATOMS * 2 + 255) / 256, 256>>>();
    split_weights<<<dim3(NLAYERS, 8), 256>>>(iW, oW);

    int nblocks = (NP + 127) / 128;   // 1954
    pairnet_mma<<<nblocks, NTHR, SMEM_BYTES>>>(
        R, idx_i, idx_j, iB, oB, oWf, oBf, out + 2 * NATOMS);

    finalize_kernel<<<(NATOMS + 255) / 256, 256>>>(Z, scales, shifts, out);
    write_nh<<<1, 1>>>(out);
}

// round 5
// speedup vs baseline: 2.7616x; 1.6134x over previous
#include <cuda_runtime.h>
#include <cuda_fp16.h>
#include <cstdint>

#define NP      250000
#define NATOMS  10000
#define NBLK    5
#define NLAYERS 20
#define NTHR    256

// smem layout (bytes)
#define BUF0_OFF   0
#define BUF1_OFF   32768
#define SPILL_OFF  65536          // 64KB x-spill
#define BIAS_OFF   131072
#define WF_OFF     131584
#define ER_OFF     132608
#define FC_OFF     133120
#define IDX_OFF    133632
#define SMEM_BYTES 134144

#define INV2048 4.8828125e-4f

__device__ float g_blockout[NBLK * NATOMS * 2];
__device__ float g_nh;
// pre-split, pre-swizzled weights: [L][limb][k][swizzled n]  (20*2*16384 fp16)
__device__ __align__(16) __half g_Wh[NLAYERS * 2 * 16384];

// ---------------- helpers ----------------
__device__ __forceinline__ uint32_t smem_u32(const void* p) {
    uint32_t a;
    asm("{ .reg .u64 t; cvta.to.shared.u64 t, %1; cvt.u32.u64 %0, t; }" : "=r"(a) : "l"(p));
    return a;
}
__device__ __forceinline__ void mma_f16(float* c, uint32_t a0, uint32_t a1, uint32_t a2, uint32_t a3,
                                        uint32_t b0, uint32_t b1) {
    asm volatile("mma.sync.aligned.m16n8k16.row.col.f32.f16.f16.f32 "
                 "{%0,%1,%2,%3}, {%4,%5,%6,%7}, {%8,%9}, {%0,%1,%2,%3};"
                 : "+f"(c[0]), "+f"(c[1]), "+f"(c[2]), "+f"(c[3])
                 : "r"(a0), "r"(a1), "r"(a2), "r"(a3), "r"(b0), "r"(b1));
}
__device__ __forceinline__ void ldsm4t(uint32_t addr, uint32_t& r0, uint32_t& r1, uint32_t& r2, uint32_t& r3) {
    asm volatile("ldmatrix.sync.aligned.m8n8.x4.trans.shared.b16 {%0,%1,%2,%3}, [%4];"
                 : "=r"(r0), "=r"(r1), "=r"(r2), "=r"(r3) : "r"(addr));
}
#define CP_ASYNC(dst, src) asm volatile("cp.async.cg.shared.global [%0], [%1], 16;" :: "r"(dst), "l"(src) : "memory")
#define CP_COMMIT()        asm volatile("cp.async.commit_group;" ::: "memory")
#define CP_WAIT(n)         asm volatile("cp.async.wait_group %0;" :: "n"(n) : "memory")

__device__ __forceinline__ float sspf(float x) {
    float e = __expf(-fabsf(x));
    return fmaxf(x, 0.0f) + __logf(1.0f + e) - 0.69314718055994531f;
}
// fp32 -> 2 fp16 limbs, second limb pre-scaled by 2048
__device__ __forceinline__ void split2h(float v, __half& h0, __half& h1s) {
    h0 = __float2half_rn(v);
    float r = (v - __half2float(h0)) * 2048.0f;
    h1s = __float2half_rn(r);
}
__device__ __forceinline__ uint32_t packh2(__half a, __half b) {
    __half2 t = __halves2half2(a, b);
    return *reinterpret_cast<uint32_t*>(&t);
}

// ---------------- weight prep: split + swizzle ----------------
__global__ void split_weights(const float* __restrict__ iW, const float* __restrict__ oW) {
    int L = blockIdx.x, sl = blockIdx.y;
    int b = L >> 2, l = L & 3;
    const float* W = (l < 2) ? iW + (size_t)(b * 2 + l) * 16384
                             : oW + (size_t)(b * 2 + l - 2) * 16384;
    size_t base = (size_t)L * 2 * 16384;
    for (int e = sl * 2048 + threadIdx.x; e < (sl + 1) * 2048; e += 256) {
        int k = e >> 7, n = e & 127;
        __half h0, h1s;
        split2h(W[e], h0, h1s);
        int c = (n >> 3) ^ (k & 15);
        int idx = k * 128 + c * 8 + (n & 7);
        g_Wh[base + idx]         = h0;
        g_Wh[base + 16384 + idx] = h1s;
    }
}

// ---------------- MMA phase: 4 K-chunks against one 32KB B half ----------------
struct LaneCtx { uint32_t sb; int lane_row; int lane_cadd; };

__device__ __forceinline__ void do_phase(int qbase, uint32_t bufoff,
                                         const uint32_t* A, float* C00, float* C01,
                                         const LaneCtx& lc) {
    #pragma unroll
    for (int qq = 0; qq < 4; ++qq) {
        uint32_t rowaddr = lc.sb + bufoff + (uint32_t)(qq * 16 + lc.lane_row) * 256u;
        #pragma unroll
        for (int jq = 0; jq < 4; ++jq) {
            uint32_t Bf[2][2][4];
            #pragma unroll
            for (int jp = 0; jp < 2; ++jp) {
                int c  = 2 * (2 * jq + jp) + lc.lane_cadd;
                int cp = c ^ lc.lane_row;
                uint32_t addr = rowaddr + (uint32_t)cp * 16u;
                ldsm4t(addr,          Bf[jp][0][0], Bf[jp][0][1], Bf[jp][0][2], Bf[jp][0][3]);
                ldsm4t(addr + 16384u, Bf[jp][1][0], Bf[jp][1][1], Bf[jp][1][2], Bf[jp][1][3]);
            }
            const uint32_t* A0 = A + (qbase + qq) * 8;
            const uint32_t* A1 = A0 + 4;
            #pragma unroll
            for (int cc = 0; cc < 4; ++cc) {
                int jp = cc >> 1, hf = cc & 1;
                float* c00 = &C00[(4 * jq + cc) * 4];
                float* c01 = &C01[(4 * jq + cc) * 4];
                uint32_t b00 = Bf[jp][0][hf * 2], b01 = Bf[jp][0][hf * 2 + 1];
                uint32_t b10 = Bf[jp][1][hf * 2], b11 = Bf[jp][1][hf * 2 + 1];
                mma_f16(c00, A0[0], A0[1], A0[2], A0[3], b00, b01);   // l0*w0
                mma_f16(c01, A0[0], A0[1], A0[2], A0[3], b10, b11);   // l0*w1s
                mma_f16(c01, A1[0], A1[1], A1[2], A1[3], b00, b01);   // l1s*w0
            }
        }
    }
}

// ---------------- main kernel ----------------
__global__ void __launch_bounds__(NTHR, 1)
pairnet_mma(const float* __restrict__ R,
            const int*   __restrict__ idx_i,
            const int*   __restrict__ idx_j,
            const float* __restrict__ iB, const float* __restrict__ oB,
            const float* __restrict__ oWf, const float* __restrict__ oBf,
            float* __restrict__ outRij)
{
    extern __shared__ char smem[];
    uint32_t sb = smem_u32(smem);
    float* sBias = (float*)(smem + BIAS_OFF);
    float* sWf   = (float*)(smem + WF_OFF);
    float* sEr   = (float*)(smem + ER_OFF);
    float* sFc   = (float*)(smem + FC_OFF);
    int*   sIdx  = (int*)  (smem + IDX_OFF);
    uint4* sSpill = (uint4*)(smem + SPILL_OFF);

    const int tid = threadIdx.x;
    const int w = tid >> 5, l = tid & 31;
    const int g = l >> 2, four = l & 3;
    const int p0 = blockIdx.x * 128;
    LaneCtx lc; lc.sb = sb; lc.lane_row = l & 15; lc.lane_cadd = l >> 4;

    // issue copies for layer 0 (both halves)
    {
        const char* gsrc = (const char*)g_Wh;
        #pragma unroll
        for (int h = 0; h < 2; ++h) {
            #pragma unroll
            for (int t = 0; t < 2; ++t)
                #pragma unroll
                for (int i = 0; i < 4; ++i) {
                    int idx = i * 256 + tid;
                    CP_ASYNC(sb + (uint32_t)(h * 32768 + t * 16384 + idx * 16),
                             gsrc + t * 32768 + h * 16384 + idx * 16);
                }
            CP_COMMIT();
        }
    }

    // geometry
    if (tid < 128) {
        int p = p0 + tid;
        float er = 0.0f, fc = 0.0f; int ii = 0;
        if (p < NP) {
            ii = idx_i[p];
            int jj = idx_j[p];
            float dx = R[3*jj+0] - R[3*ii+0];
            float dy = R[3*jj+1] - R[3*ii+1];
            float dz = R[3*jj+2] - R[3*ii+2];
            float rij = sqrtf(dx*dx + dy*dy + dz*dz + 1e-12f);
            outRij[p] = rij;
            if (rij < 10.0f) {
                float xq = rij * 0.1f;
                float x2 = xq*xq, x3 = x2*xq, x4 = x2*x2, x5 = x4*xq;
                fc = 1.0f - 6.0f*x5 + 15.0f*x4 - 10.0f*x3;
            }
            er = expf(-rij);
        }
        sIdx[tid] = ii; sEr[tid] = er; sFc[tid] = fc;
    }
    __syncthreads();

    // basis -> A fragments (2 limbs, registers)
    uint32_t A[64];
    {
        const float MU0    = 4.5399929762484854e-05f;
        const float MUSTEP = 7.8736582670224e-03f;
        const float WIDTH  = 4096.37195f;
        float er0 = sEr[16*w + g],     fc0 = sFc[16*w + g];
        float er8 = sEr[16*w + g + 8], fc8 = sFc[16*w + g + 8];
        #pragma unroll
        for (int q = 0; q < 8; ++q) {
            #pragma unroll
            for (int jj = 0; jj < 2; ++jj) {
                int k0 = 16*q + 8*jj + 2*four;
                float m0 = MU0 + (float)k0 * MUSTEP;
                float m1 = MU0 + (float)(k0+1) * MUSTEP;
                float d;
                d = er0 - m0; float e0 = fc0 * __expf(-WIDTH * d * d);
                d = er0 - m1; float e1 = fc0 * __expf(-WIDTH * d * d);
                d = er8 - m0; float e2 = fc8 * __expf(-WIDTH * d * d);
                d = er8 - m1; float e3 = fc8 * __expf(-WIDTH * d * d);
                __half h[4][2];
                split2h(e0, h[0][0], h[0][1]); split2h(e1, h[1][0], h[1][1]);
                split2h(e2, h[2][0], h[2][1]); split2h(e3, h[3][0], h[3][1]);
                #pragma unroll
                for (int t = 0; t < 2; ++t) {
                    A[q*8 + t*4 + jj*2 + 0] = packh2(h[0][t], h[1][t]);
                    A[q*8 + t*4 + jj*2 + 1] = packh2(h[2][t], h[3][t]);
                }
            }
        }
    }

    float C00[64], C01[64];

    #pragma unroll 1
    for (int L = 0; L < NLAYERS; ++L) {
        const int b = L >> 2, lay = L & 3;
        const float* bp = (lay < 2) ? iB + (b*2 + lay)*128 : oB + (b*2 + lay - 2)*128;
        if (tid < 128) sBias[tid] = bp[tid];
        if (lay == 3) sWf[tid] = oWf[b*256 + tid];

        #pragma unroll
        for (int i = 0; i < 64; ++i) { C00[i] = 0.0f; C01[i] = 0.0f; }

        CP_WAIT(1);
        __syncthreads();
        do_phase(0, BUF0_OFF, A, C00, C01, lc);

        CP_WAIT(0);
        __syncthreads();
        if (L < NLAYERS - 1) {   // prefetch next layer's half 0
            const char* gsrc = (const char*)g_Wh + (size_t)(L + 1) * 65536;
            #pragma unroll
            for (int t = 0; t < 2; ++t)
                #pragma unroll
                for (int i = 0; i < 4; ++i) {
                    int idx = i * 256 + tid;
                    CP_ASYNC(sb + (uint32_t)(t * 16384 + idx * 16),
                             gsrc + t * 32768 + idx * 16);
                }
            CP_COMMIT();
        }
        do_phase(4, BUF1_OFF, A, C00, C01, lc);

        if (lay == 2) {   // spill x before overwriting A with y
            #pragma unroll
            for (int i = 0; i < 16; ++i) sSpill[i * 256 + tid] = ((uint4*)A)[i];
        }

        if (lay < 3) {
            // epilogue: combine limb accumulators, bias + ssp + split -> new A
            #pragma unroll
            for (int q = 0; q < 8; ++q) {
                #pragma unroll
                for (int jj = 0; jj < 2; ++jj) {
                    int j = 2*q + jj;
                    float2 bb = *(const float2*)&sBias[j*8 + four*2];
                    float e0 = sspf(fmaf(C01[j*4+0], INV2048, C00[j*4+0]) + bb.x);
                    float e1 = sspf(fmaf(C01[j*4+1], INV2048, C00[j*4+1]) + bb.y);
                    float e2 = sspf(fmaf(C01[j*4+2], INV2048, C00[j*4+2]) + bb.x);
                    float e3 = sspf(fmaf(C01[j*4+3], INV2048, C00[j*4+3]) + bb.y);
                    __half h[4][2];
                    split2h(e0, h[0][0], h[0][1]); split2h(e1, h[1][0], h[1][1]);
                    split2h(e2, h[2][0], h[2][1]); split2h(e3, h[3][0], h[3][1]);
                    #pragma unroll
                    for (int t = 0; t < 2; ++t) {
                        A[q*8 + t*4 + jj*2 + 0] = packh2(h[0][t], h[1][t]);
                        A[q*8 + t*4 + jj*2 + 1] = packh2(h[2][t], h[3][t]);
                    }
                }
            }
        } else {
            // head: y2 = ssp(C + bias); out = y2 @ Wf + oBf; segment atomics
            float s00 = 0.f, s01 = 0.f, s10 = 0.f, s11 = 0.f;
            #pragma unroll
            for (int j = 0; j < 16; ++j) {
                int col0 = j*8 + four*2;
                float2 bb = *(const float2*)&sBias[col0];
                float e0 = sspf(fmaf(C01[j*4+0], INV2048, C00[j*4+0]) + bb.x);
                float e1 = sspf(fmaf(C01[j*4+1], INV2048, C00[j*4+1]) + bb.y);
                float e2 = sspf(fmaf(C01[j*4+2], INV2048, C00[j*4+2]) + bb.x);
                float e3 = sspf(fmaf(C01[j*4+3], INV2048, C00[j*4+3]) + bb.y);
                float2 w0 = *(const float2*)&sWf[col0*2];
                float2 w1 = *(const float2*)&sWf[col0*2 + 2];
                s00 = fmaf(e0, w0.x, fmaf(e1, w1.x, s00));
                s01 = fmaf(e0, w0.y, fmaf(e1, w1.y, s01));
                s10 = fmaf(e2, w0.x, fmaf(e3, w1.x, s10));
                s11 = fmaf(e2, w0.y, fmaf(e3, w1.y, s11));
            }
            #pragma unroll
            for (int d = 1; d <= 2; d <<= 1) {
                s00 += __shfl_xor_sync(0xffffffffu, s00, d);
                s01 += __shfl_xor_sync(0xffffffffu, s01, d);
                s10 += __shfl_xor_sync(0xffffffffu, s10, d);
                s11 += __shfl_xor_sync(0xffffffffu, s11, d);
            }
            if (four == 0) {
                float bf0 = __ldg(&oBf[b*2]), bf1 = __ldg(&oBf[b*2+1]);
                int r0 = 16*w + g, r1 = r0 + 8;
                if (p0 + r0 < NP) {
                    int a = sIdx[r0];
                    atomicAdd(&g_blockout[(b*NATOMS + a)*2 + 0], s00 + bf0);
                    atomicAdd(&g_blockout[(b*NATOMS + a)*2 + 1], s01 + bf1);
                }
                if (p0 + r1 < NP) {
                    int a = sIdx[r1];
                    atomicAdd(&g_blockout[(b*NATOMS + a)*2 + 0], s10 + bf0);
                    atomicAdd(&g_blockout[(b*NATOMS + a)*2 + 1], s11 + bf1);
                }
            }
            // restore x for next block
            if (L < NLAYERS - 1) {
                #pragma unroll
                for (int i = 0; i < 16; ++i) ((uint4*)A)[i] = sSpill[i * 256 + tid];
            }
        }

        __syncthreads();
        if (L < NLAYERS - 1) {   // prefetch next layer's half 1
            const char* gsrc = (const char*)g_Wh + (size_t)(L + 1) * 65536;
            #pragma unroll
            for (int t = 0; t < 2; ++t)
                #pragma unroll
                for (int i = 0; i < 4; ++i) {
                    int idx = i * 256 + tid;
                    CP_ASYNC(sb + (uint32_t)(32768 + t * 16384 + idx * 16),
                             gsrc + t * 32768 + 16384 + idx * 16);
                }
            CP_COMMIT();
        }
    }
}

// ---------------- zero / finalize ----------------
__global__ void zero_scratch() {
    int i = blockIdx.x * blockDim.x + threadIdx.x;
    if (i < NBLK * NATOMS * 2) g_blockout[i] = 0.0f;
    if (i == 0) g_nh = 0.0f;
}

__global__ void finalize_kernel(const int* __restrict__ Z,
                                const float* __restrict__ scales,
                                const float* __restrict__ shifts,
                                float* __restrict__ out)
{
    int a = blockIdx.x * blockDim.x + threadIdx.x;
    float local = 0.0f;
    if (a < NATOMS) {
        int z = Z[a];
        #pragma unroll
        for (int o = 0; o < 2; ++o) {
            float tot = 0.0f, last2 = 0.0f;
            #pragma unroll
            for (int b = 0; b < NBLK; ++b) {
                float v = g_blockout[(b * NATOMS + a) * 2 + o];
                tot += v;
                float v2 = v * v;
                if (b > 0) local += v2 / (v2 + last2 + 1e-7f);
                last2 = v2;
            }
            out[a * 2 + o] = tot * scales[o * 95 + z] + shifts[o * 95 + z];
        }
    }
    __shared__ float red[256];
    red[threadIdx.x] = local;
    __syncthreads();
    #pragma unroll
    for (int s = 128; s > 0; s >>= 1) {
        if (threadIdx.x < s) red[threadIdx.x] += red[threadIdx.x + s];
        __syncthreads();
    }
    if (threadIdx.x == 0) atomicAdd(&g_nh, red[0]);
}

__global__ void write_nh(float* __restrict__ out) {
    out[NATOMS * 2 + NP] = g_nh * (1.0f / 20000.0f);
}

// ---------------- launch ----------------
extern "C" void kernel_launch(void* const* d_in, const int* in_sizes, int n_in,
                              void* d_out, int out_size)
{
    const int*   Z      = (const int*)  d_in[0];
    const float* R      = (const float*)d_in[1];
    const int*   idx_i  = (const int*)  d_in[2];
    const int*   idx_j  = (const int*)  d_in[3];
    const float* iW     = (const float*)d_in[4];
    const float* iB     = (const float*)d_in[5];
    const float* oW     = (const float*)d_in[6];
    const float* oB     = (const float*)d_in[7];
    const float* oWf    = (const float*)d_in[8];
    const float* oBf    = (const float*)d_in[9];
    const float* scales = (const float*)d_in[10];
    const float* shifts = (const float*)d_in[11];
    float* out = (float*)d_out;

    cudaFuncSetAttribute(pairnet_mma,
                         cudaFuncAttributeMaxDynamicSharedMemorySize, SMEM_BYTES);

    zero_scratch<<<(NBLK * NATOMS * 2 + 255) / 256, 256>>>();
    split_weights<<<dim3(NLAYERS, 8), 256>>>(iW, oW);

    int nblocks = (NP + 127) / 128;   // 1954
    pairnet_mma<<<nblocks, NTHR, SMEM_BYTES>>>(
        R, idx_i, idx_j, iB, oB, oWf, oBf, out + 2 * NATOMS);

    finalize_kernel<<<(NATOMS + 255) / 256, 256>>>(Z, scales, shifts, out);
    write_nh<<<1, 1>>>(out);
}

// round 6
// speedup vs baseline: 2.7983x; 1.0133x over previous
#include <cuda_runtime.h>
#include <cuda_fp16.h>
#include <cstdint>

#define NP      250000
#define NATOMS  10000
#define NBLK    5
#define NLAYERS 20
#define NTHR    256

// smem layout (bytes)
#define BUF0_OFF   0
#define BUF1_OFF   32768
#define SPILL_OFF  65536          // 64KB x-spill
#define BIAS_OFF   131072
#define WF_OFF     131584
#define ER_OFF     132608
#define FC_OFF     133120
#define IDX_OFF    133632
#define SMEM_BYTES 134144

#define INV2048 4.8828125e-4f

__device__ float g_blockout[NBLK * NATOMS * 2];
__device__ float g_nh;
// pre-split, pre-swizzled weights: [L][limb][k][swizzled n]  (20*2*16384 fp16)
__device__ __align__(16) __half g_Wh[NLAYERS * 2 * 16384];

// ---------------- helpers ----------------
__device__ __forceinline__ uint32_t smem_u32(const void* p) {
    uint32_t a;
    asm("{ .reg .u64 t; cvta.to.shared.u64 t, %1; cvt.u32.u64 %0, t; }" : "=r"(a) : "l"(p));
    return a;
}
// fp32-accumulator MMA (main term)
__device__ __forceinline__ void mma_f16(float* c, uint32_t a0, uint32_t a1, uint32_t a2, uint32_t a3,
                                        uint32_t b0, uint32_t b1) {
    asm volatile("mma.sync.aligned.m16n8k16.row.col.f32.f16.f16.f32 "
                 "{%0,%1,%2,%3}, {%4,%5,%6,%7}, {%8,%9}, {%0,%1,%2,%3};"
                 : "+f"(c[0]), "+f"(c[1]), "+f"(c[2]), "+f"(c[3])
                 : "r"(a0), "r"(a1), "r"(a2), "r"(a3), "r"(b0), "r"(b1));
}
// fp16-accumulator MMA (cross terms — scaled by 2^11, error budget 2^-22)
__device__ __forceinline__ void mma_f16acc(uint32_t* c, uint32_t a0, uint32_t a1, uint32_t a2, uint32_t a3,
                                           uint32_t b0, uint32_t b1) {
    asm volatile("mma.sync.aligned.m16n8k16.row.col.f16.f16.f16.f16 "
                 "{%0,%1}, {%2,%3,%4,%5}, {%6,%7}, {%0,%1};"
                 : "+r"(c[0]), "+r"(c[1])
                 : "r"(a0), "r"(a1), "r"(a2), "r"(a3), "r"(b0), "r"(b1));
}
__device__ __forceinline__ void ldsm4t(uint32_t addr, uint32_t& r0, uint32_t& r1, uint32_t& r2, uint32_t& r3) {
    asm volatile("ldmatrix.sync.aligned.m8n8.x4.trans.shared.b16 {%0,%1,%2,%3}, [%4];"
                 : "=r"(r0), "=r"(r1), "=r"(r2), "=r"(r3) : "r"(addr));
}
#define CP_ASYNC(dst, src) asm volatile("cp.async.cg.shared.global [%0], [%1], 16;" :: "r"(dst), "l"(src) : "memory")
#define CP_COMMIT()        asm volatile("cp.async.commit_group;" ::: "memory")
#define CP_WAIT(n)         asm volatile("cp.async.wait_group %0;" :: "n"(n) : "memory")

__device__ __forceinline__ float sspf(float x) {
    float e = __expf(-fabsf(x));
    return fmaxf(x, 0.0f) + __logf(1.0f + e) - 0.69314718055994531f;
}
// fp32 -> 2 fp16 limbs, second limb pre-scaled by 2048
__device__ __forceinline__ void split2h(float v, __half& h0, __half& h1s) {
    h0 = __float2half_rn(v);
    float r = (v - __half2float(h0)) * 2048.0f;
    h1s = __float2half_rn(r);
}
__device__ __forceinline__ uint32_t packh2(__half a, __half b) {
    __half2 t = __halves2half2(a, b);
    return *reinterpret_cast<uint32_t*>(&t);
}

// ---------------- weight prep: split + swizzle ----------------
__global__ void split_weights(const float* __restrict__ iW, const float* __restrict__ oW) {
    int L = blockIdx.x, sl = blockIdx.y;
    int b = L >> 2, l = L & 3;
    const float* W = (l < 2) ? iW + (size_t)(b * 2 + l) * 16384
                             : oW + (size_t)(b * 2 + l - 2) * 16384;
    size_t base = (size_t)L * 2 * 16384;
    for (int e = sl * 2048 + threadIdx.x; e < (sl + 1) * 2048; e += 256) {
        int k = e >> 7, n = e & 127;
        __half h0, h1s;
        split2h(W[e], h0, h1s);
        int c = (n >> 3) ^ (k & 15);
        int idx = k * 128 + c * 8 + (n & 7);
        g_Wh[base + idx]         = h0;
        g_Wh[base + 16384 + idx] = h1s;
    }
}

// ---------------- MMA phase: 4 K-chunks against one 32KB B half ----------------
struct LaneCtx { uint32_t sb; int lane_row; int lane_cadd; };

__device__ __forceinline__ void do_phase(int qbase, uint32_t bufoff,
                                         const uint32_t* A, float* C00, uint32_t* C01h,
                                         const LaneCtx& lc) {
    #pragma unroll
    for (int qq = 0; qq < 4; ++qq) {
        uint32_t rowaddr = lc.sb + bufoff + (uint32_t)(qq * 16 + lc.lane_row) * 256u;
        #pragma unroll
        for (int jq = 0; jq < 4; ++jq) {
            uint32_t Bf[2][2][4];
            #pragma unroll
            for (int jp = 0; jp < 2; ++jp) {
                int c  = 2 * (2 * jq + jp) + lc.lane_cadd;
                int cp = c ^ lc.lane_row;
                uint32_t addr = rowaddr + (uint32_t)cp * 16u;
                ldsm4t(addr,          Bf[jp][0][0], Bf[jp][0][1], Bf[jp][0][2], Bf[jp][0][3]);
                ldsm4t(addr + 16384u, Bf[jp][1][0], Bf[jp][1][1], Bf[jp][1][2], Bf[jp][1][3]);
            }
            const uint32_t* A0 = A + (qbase + qq) * 8;
            const uint32_t* A1 = A0 + 4;
            #pragma unroll
            for (int cc = 0; cc < 4; ++cc) {
                int jp = cc >> 1, hf = cc & 1;
                float*    c00 = &C00[(4 * jq + cc) * 4];
                uint32_t* c01 = &C01h[(4 * jq + cc) * 2];
                uint32_t b00 = Bf[jp][0][hf * 2], b01 = Bf[jp][0][hf * 2 + 1];
                uint32_t b10 = Bf[jp][1][hf * 2], b11 = Bf[jp][1][hf * 2 + 1];
                mma_f16(c00, A0[0], A0[1], A0[2], A0[3], b00, b01);      // l0*w0   (f32 acc)
                mma_f16acc(c01, A0[0], A0[1], A0[2], A0[3], b10, b11);   // l0*w1s  (f16 acc)
                mma_f16acc(c01, A1[0], A1[1], A1[2], A1[3], b00, b01);   // l1s*w0  (f16 acc)
            }
        }
    }
}

// combine limb accumulators -> fp32 value (pre-bias)
__device__ __forceinline__ void combine4(const float* c00, const uint32_t* c01h, float* v) {
    float2 lo = __half22float2(*reinterpret_cast<const __half2*>(&c01h[0]));
    float2 hi = __half22float2(*reinterpret_cast<const __half2*>(&c01h[1]));
    v[0] = fmaf(lo.x, INV2048, c00[0]);
    v[1] = fmaf(lo.y, INV2048, c00[1]);
    v[2] = fmaf(hi.x, INV2048, c00[2]);
    v[3] = fmaf(hi.y, INV2048, c00[3]);
}

// ---------------- main kernel ----------------
__global__ void __launch_bounds__(NTHR, 1)
pairnet_mma(const float* __restrict__ R,
            const int*   __restrict__ idx_i,
            const int*   __restrict__ idx_j,
            const float* __restrict__ iB, const float* __restrict__ oB,
            const float* __restrict__ oWf, const float* __restrict__ oBf,
            float* __restrict__ outRij)
{
    extern __shared__ char smem[];
    uint32_t sb = smem_u32(smem);
    float* sBias = (float*)(smem + BIAS_OFF);
    float* sWf   = (float*)(smem + WF_OFF);
    float* sEr   = (float*)(smem + ER_OFF);
    float* sFc   = (float*)(smem + FC_OFF);
    int*   sIdx  = (int*)  (smem + IDX_OFF);
    uint4* sSpill = (uint4*)(smem + SPILL_OFF);

    const int tid = threadIdx.x;
    const int w = tid >> 5, l = tid & 31;
    const int g = l >> 2, four = l & 3;
    const int p0 = blockIdx.x * 128;
    LaneCtx lc; lc.sb = sb; lc.lane_row = l & 15; lc.lane_cadd = l >> 4;

    // issue copies for layer 0 (both halves)
    {
        const char* gsrc = (const char*)g_Wh;
        #pragma unroll
        for (int h = 0; h < 2; ++h) {
            #pragma unroll
            for (int t = 0; t < 2; ++t)
                #pragma unroll
                for (int i = 0; i < 4; ++i) {
                    int idx = i * 256 + tid;
                    CP_ASYNC(sb + (uint32_t)(h * 32768 + t * 16384 + idx * 16),
                             gsrc + t * 32768 + h * 16384 + idx * 16);
                }
            CP_COMMIT();
        }
    }

    // geometry
    if (tid < 128) {
        int p = p0 + tid;
        float er = 0.0f, fc = 0.0f; int ii = 0;
        if (p < NP) {
            ii = idx_i[p];
            int jj = idx_j[p];
            float dx = R[3*jj+0] - R[3*ii+0];
            float dy = R[3*jj+1] - R[3*ii+1];
            float dz = R[3*jj+2] - R[3*ii+2];
            float rij = sqrtf(dx*dx + dy*dy + dz*dz + 1e-12f);
            outRij[p] = rij;
            if (rij < 10.0f) {
                float xq = rij * 0.1f;
                float x2 = xq*xq, x3 = x2*xq, x4 = x2*x2, x5 = x4*xq;
                fc = 1.0f - 6.0f*x5 + 15.0f*x4 - 10.0f*x3;
            }
            er = expf(-rij);
        }
        sIdx[tid] = ii; sEr[tid] = er; sFc[tid] = fc;
    }
    __syncthreads();

    // basis -> A fragments (2 limbs, registers)
    uint32_t A[64];
    {
        const float MU0    = 4.5399929762484854e-05f;
        const float MUSTEP = 7.8736582670224e-03f;
        const float WIDTH  = 4096.37195f;
        float er0 = sEr[16*w + g],     fc0 = sFc[16*w + g];
        float er8 = sEr[16*w + g + 8], fc8 = sFc[16*w + g + 8];
        #pragma unroll
        for (int q = 0; q < 8; ++q) {
            #pragma unroll
            for (int jj = 0; jj < 2; ++jj) {
                int k0 = 16*q + 8*jj + 2*four;
                float m0 = MU0 + (float)k0 * MUSTEP;
                float m1 = MU0 + (float)(k0+1) * MUSTEP;
                float d;
                d = er0 - m0; float e0 = fc0 * __expf(-WIDTH * d * d);
                d = er0 - m1; float e1 = fc0 * __expf(-WIDTH * d * d);
                d = er8 - m0; float e2 = fc8 * __expf(-WIDTH * d * d);
                d = er8 - m1; float e3 = fc8 * __expf(-WIDTH * d * d);
                __half h[4][2];
                split2h(e0, h[0][0], h[0][1]); split2h(e1, h[1][0], h[1][1]);
                split2h(e2, h[2][0], h[2][1]); split2h(e3, h[3][0], h[3][1]);
                #pragma unroll
                for (int t = 0; t < 2; ++t) {
                    A[q*8 + t*4 + jj*2 + 0] = packh2(h[0][t], h[1][t]);
                    A[q*8 + t*4 + jj*2 + 1] = packh2(h[2][t], h[3][t]);
                }
            }
        }
    }

    float C00[64];
    uint32_t C01h[32];

    #pragma unroll 1
    for (int L = 0; L < NLAYERS; ++L) {
        const int b = L >> 2, lay = L & 3;
        const float* bp = (lay < 2) ? iB + (b*2 + lay)*128 : oB + (b*2 + lay - 2)*128;
        if (tid < 128) sBias[tid] = bp[tid];
        if (lay == 3) sWf[tid] = oWf[b*256 + tid];

        #pragma unroll
        for (int i = 0; i < 64; ++i) C00[i] = 0.0f;
        #pragma unroll
        for (int i = 0; i < 32; ++i) C01h[i] = 0u;

        CP_WAIT(1);
        __syncthreads();
        do_phase(0, BUF0_OFF, A, C00, C01h, lc);

        CP_WAIT(0);
        __syncthreads();
        if (L < NLAYERS - 1) {   // prefetch next layer's half 0
            const char* gsrc = (const char*)g_Wh + (size_t)(L + 1) * 65536;
            #pragma unroll
            for (int t = 0; t < 2; ++t)
                #pragma unroll
                for (int i = 0; i < 4; ++i) {
                    int idx = i * 256 + tid;
                    CP_ASYNC(sb + (uint32_t)(t * 16384 + idx * 16),
                             gsrc + t * 32768 + idx * 16);
                }
            CP_COMMIT();
        }
        do_phase(4, BUF1_OFF, A, C00, C01h, lc);

        if (lay == 2) {   // spill x before overwriting A with y
            #pragma unroll
            for (int i = 0; i < 16; ++i) sSpill[i * 256 + tid] = ((uint4*)A)[i];
        }

        if (lay < 3) {
            // epilogue: combine limb accumulators, bias + ssp + split -> new A
            #pragma unroll
            for (int q = 0; q < 8; ++q) {
                #pragma unroll
                for (int jj = 0; jj < 2; ++jj) {
                    int j = 2*q + jj;
                    float2 bb = *(const float2*)&sBias[j*8 + four*2];
                    float v[4];
                    combine4(&C00[j*4], &C01h[j*2], v);
                    float e0 = sspf(v[0] + bb.x);
                    float e1 = sspf(v[1] + bb.y);
                    float e2 = sspf(v[2] + bb.x);
                    float e3 = sspf(v[3] + bb.y);
                    __half h[4][2];
                    split2h(e0, h[0][0], h[0][1]); split2h(e1, h[1][0], h[1][1]);
                    split2h(e2, h[2][0], h[2][1]); split2h(e3, h[3][0], h[3][1]);
                    #pragma unroll
                    for (int t = 0; t < 2; ++t) {
                        A[q*8 + t*4 + jj*2 + 0] = packh2(h[0][t], h[1][t]);
                        A[q*8 + t*4 + jj*2 + 1] = packh2(h[2][t], h[3][t]);
                    }
                }
            }
        } else {
            // head: y2 = ssp(C + bias); out = y2 @ Wf + oBf; segment atomics
            float s00 = 0.f, s01 = 0.f, s10 = 0.f, s11 = 0.f;
            #pragma unroll
            for (int j = 0; j < 16; ++j) {
                int col0 = j*8 + four*2;
                float2 bb = *(const float2*)&sBias[col0];
                float v[4];
                combine4(&C00[j*4], &C01h[j*2], v);
                float e0 = sspf(v[0] + bb.x);
                float e1 = sspf(v[1] + bb.y);
                float e2 = sspf(v[2] + bb.x);
                float e3 = sspf(v[3] + bb.y);
                float2 w0 = *(const float2*)&sWf[col0*2];
                float2 w1 = *(const float2*)&sWf[col0*2 + 2];
                s00 = fmaf(e0, w0.x, fmaf(e1, w1.x, s00));
                s01 = fmaf(e0, w0.y, fmaf(e1, w1.y, s01));
                s10 = fmaf(e2, w0.x, fmaf(e3, w1.x, s10));
                s11 = fmaf(e2, w0.y, fmaf(e3, w1.y, s11));
            }
            #pragma unroll
            for (int d = 1; d <= 2; d <<= 1) {
                s00 += __shfl_xor_sync(0xffffffffu, s00, d);
                s01 += __shfl_xor_sync(0xffffffffu, s01, d);
                s10 += __shfl_xor_sync(0xffffffffu, s10, d);
                s11 += __shfl_xor_sync(0xffffffffu, s11, d);
            }
            if (four == 0) {
                float bf0 = __ldg(&oBf[b*2]), bf1 = __ldg(&oBf[b*2+1]);
                int r0 = 16*w + g, r1 = r0 + 8;
                if (p0 + r0 < NP) {
                    int a = sIdx[r0];
                    atomicAdd(&g_blockout[(b*NATOMS + a)*2 + 0], s00 + bf0);
                    atomicAdd(&g_blockout[(b*NATOMS + a)*2 + 1], s01 + bf1);
                }
                if (p0 + r1 < NP) {
                    int a = sIdx[r1];
                    atomicAdd(&g_blockout[(b*NATOMS + a)*2 + 0], s10 + bf0);
                    atomicAdd(&g_blockout[(b*NATOMS + a)*2 + 1], s11 + bf1);
                }
            }
            // restore x for next block
            if (L < NLAYERS - 1) {
                #pragma unroll
                for (int i = 0; i < 16; ++i) ((uint4*)A)[i] = sSpill[i * 256 + tid];
            }
        }

        __syncthreads();
        if (L < NLAYERS - 1) {   // prefetch next layer's half 1
            const char* gsrc = (const char*)g_Wh + (size_t)(L + 1) * 65536;
            #pragma unroll
            for (int t = 0; t < 2; ++t)
                #pragma unroll
                for (int i = 0; i < 4; ++i) {
                    int idx = i * 256 + tid;
                    CP_ASYNC(sb + (uint32_t)(32768 + t * 16384 + idx * 16),
                             gsrc + t * 32768 + 16384 + idx * 16);
                }
            CP_COMMIT();
        }
    }
}

// ---------------- zero / finalize ----------------
__global__ void zero_scratch() {
    int i = blockIdx.x * blockDim.x + threadIdx.x;
    if (i < NBLK * NATOMS * 2) g_blockout[i] = 0.0f;
    if (i == 0) g_nh = 0.0f;
}

__global__ void finalize_kernel(const int* __restrict__ Z,
                                const float* __restrict__ scales,
                                const float* __restrict__ shifts,
                                float* __restrict__ out)
{
    int a = blockIdx.x * blockDim.x + threadIdx.x;
    float local = 0.0f;
    if (a < NATOMS) {
        int z = Z[a];
        #pragma unroll
        for (int o = 0; o < 2; ++o) {
            float tot = 0.0f, last2 = 0.0f;
            #pragma unroll
            for (int b = 0; b < NBLK; ++b) {
                float v = g_blockout[(b * NATOMS + a) * 2 + o];
                tot += v;
                float v2 = v * v;
                if (b > 0) local += v2 / (v2 + last2 + 1e-7f);
                last2 = v2;
            }
            out[a * 2 + o] = tot * scales[o * 95 + z] + shifts[o * 95 + z];
        }
    }
    __shared__ float red[256];
    red[threadIdx.x] = local;
    __syncthreads();
    #pragma unroll
    for (int s = 128; s > 0; s >>= 1) {
        if (threadIdx.x < s) red[threadIdx.x] += red[threadIdx.x + s];
        __syncthreads();
    }
    if (threadIdx.x == 0) atomicAdd(&g_nh, red[0]);
}

__global__ void write_nh(float* __restrict__ out) {
    out[NATOMS * 2 + NP] = g_nh * (1.0f / 20000.0f);
}

// ---------------- launch ----------------
extern "C" void kernel_launch(void* const* d_in, const int* in_sizes, int n_in,
                              void* d_out, int out_size)
{
    const int*   Z      = (const int*)  d_in[0];
    const float* R      = (const float*)d_in[1];
    const int*   idx_i  = (const int*)  d_in[2];
    const int*   idx_j  = (const int*)  d_in[3];
    const float* iW     = (const float*)d_in[4];
    const float* iB     = (const float*)d_in[5];
    const float* oW     = (const float*)d_in[6];
    const float* oB     = (const float*)d_in[7];
    const float* oWf    = (const float*)d_in[8];
    const float* oBf    = (const float*)d_in[9];
    const float* scales = (const float*)d_in[10];
    const float* shifts = (const float*)d_in[11];
    float* out = (float*)d_out;

    cudaFuncSetAttribute(pairnet_mma,
                         cudaFuncAttributeMaxDynamicSharedMemorySize, SMEM_BYTES);

    zero_scratch<<<(NBLK * NATOMS * 2 + 255) / 256, 256>>>();
    split_weights<<<dim3(NLAYERS, 8), 256>>>(iW, oW);

    int nblocks = (NP + 127) / 128;   // 1954
    pairnet_mma<<<nblocks, NTHR, SMEM_BYTES>>>(
        R, idx_i, idx_j, iB, oB, oWf, oBf, out + 2 * NATOMS);

    finalize_kernel<<<(NATOMS + 255) / 256, 256>>>(Z, scales, shifts, out);
    write_nh<<<1, 1>>>(out);
}

// round 7
// speedup vs baseline: 2.8902x; 1.0328x over previous
#include <cuda_runtime.h>
#include <cuda_fp16.h>
#include <cstdint>

#define NP      250000
#define NATOMS  10000
#define NBLK    5
#define NLAYERS 20
#define NTHR    256

// smem layout (bytes): 2 x 64KB layer slots | 64KB x-spill | control
#define SLOT_BYTES 65536
#define SPILL_OFF  131072
#define BIAS_OFF   196608
#define WF_OFF     197120
#define ER_OFF     198144
#define FC_OFF     198656
#define IDX_OFF    199168
#define SMEM_BYTES 199680

#define INV2048 4.8828125e-4f

__device__ float g_blockout[NBLK * NATOMS * 2];
__device__ float g_nh;
// pre-split, pre-swizzled weights: [L][limb][k][swizzled n]  (20*2*16384 fp16)
__device__ __align__(16) __half g_Wh[NLAYERS * 2 * 16384];

// ---------------- helpers ----------------
__device__ __forceinline__ uint32_t smem_u32(const void* p) {
    uint32_t a;
    asm("{ .reg .u64 t; cvta.to.shared.u64 t, %1; cvt.u32.u64 %0, t; }" : "=r"(a) : "l"(p));
    return a;
}
__device__ __forceinline__ void mma_f16(float* c, uint32_t a0, uint32_t a1, uint32_t a2, uint32_t a3,
                                        uint32_t b0, uint32_t b1) {
    asm volatile("mma.sync.aligned.m16n8k16.row.col.f32.f16.f16.f32 "
                 "{%0,%1,%2,%3}, {%4,%5,%6,%7}, {%8,%9}, {%0,%1,%2,%3};"
                 : "+f"(c[0]), "+f"(c[1]), "+f"(c[2]), "+f"(c[3])
                 : "r"(a0), "r"(a1), "r"(a2), "r"(a3), "r"(b0), "r"(b1));
}
__device__ __forceinline__ void mma_f16acc(uint32_t* c, uint32_t a0, uint32_t a1, uint32_t a2, uint32_t a3,
                                           uint32_t b0, uint32_t b1) {
    asm volatile("mma.sync.aligned.m16n8k16.row.col.f16.f16.f16.f16 "
                 "{%0,%1}, {%2,%3,%4,%5}, {%6,%7}, {%0,%1};"
                 : "+r"(c[0]), "+r"(c[1])
                 : "r"(a0), "r"(a1), "r"(a2), "r"(a3), "r"(b0), "r"(b1));
}
__device__ __forceinline__ void ldsm4t(uint32_t addr, uint32_t& r0, uint32_t& r1, uint32_t& r2, uint32_t& r3) {
    asm volatile("ldmatrix.sync.aligned.m8n8.x4.trans.shared.b16 {%0,%1,%2,%3}, [%4];"
                 : "=r"(r0), "=r"(r1), "=r"(r2), "=r"(r3) : "r"(addr));
}
#define CP_ASYNC(dst, src) asm volatile("cp.async.cg.shared.global [%0], [%1], 16;" :: "r"(dst), "l"(src) : "memory")
#define CP_COMMIT()        asm volatile("cp.async.commit_group;" ::: "memory")
#define CP_WAIT(n)         asm volatile("cp.async.wait_group %0;" :: "n"(n) : "memory")

// fast ssp: valid for |x| well below fp32 exp overflow (pre-acts are O(1) here;
// clamp is a pure inf-guard). log(1+e^x) - ln2, 2 MUFU + ~4 ALU.
__device__ __forceinline__ float sspf(float x) {
    float e = __expf(fminf(x, 60.0f));
    return __logf(1.0f + e) - 0.69314718055994531f;
}
// pairwise fp32 -> fp16 limb0 (packed), residuals scaled by 2048 -> limb1 (packed)
__device__ __forceinline__ void split2h_pair(float v0, float v1, uint32_t& u0, uint32_t& u1) {
    __half2 h0 = __float22half2_rn(make_float2(v0, v1));
    u0 = *reinterpret_cast<uint32_t*>(&h0);
    float2 f = __half22float2(h0);
    __half2 h1 = __float22half2_rn(make_float2((v0 - f.x) * 2048.0f, (v1 - f.y) * 2048.0f));
    u1 = *reinterpret_cast<uint32_t*>(&h1);
}
// combine limb accumulators -> 4 fp32 values (pre-bias)
__device__ __forceinline__ void combine4(const float* c00, const uint32_t* c01h, float* v) {
    float2 lo = __half22float2(*reinterpret_cast<const __half2*>(&c01h[0]));
    float2 hi = __half22float2(*reinterpret_cast<const __half2*>(&c01h[1]));
    v[0] = fmaf(lo.x, INV2048, c00[0]);
    v[1] = fmaf(lo.y, INV2048, c00[1]);
    v[2] = fmaf(hi.x, INV2048, c00[2]);
    v[3] = fmaf(hi.y, INV2048, c00[3]);
}

// ---------------- weight prep: split + swizzle ----------------
__global__ void split_weights(const float* __restrict__ iW, const float* __restrict__ oW) {
    int L = blockIdx.x, sl = blockIdx.y;
    int b = L >> 2, l = L & 3;
    const float* W = (l < 2) ? iW + (size_t)(b * 2 + l) * 16384
                             : oW + (size_t)(b * 2 + l - 2) * 16384;
    size_t base = (size_t)L * 2 * 16384;
    for (int e = sl * 2048 + threadIdx.x; e < (sl + 1) * 2048; e += 256) {
        int k = e >> 7, n = e & 127;
        float v = W[e];
        __half h0 = __float2half_rn(v);
        __half h1 = __float2half_rn((v - __half2float(h0)) * 2048.0f);
        int c = (n >> 3) ^ (k & 15);
        int idx = k * 128 + c * 8 + (n & 7);
        g_Wh[base + idx]         = h0;
        g_Wh[base + 16384 + idx] = h1;
    }
}

// ---------------- issue one full layer copy (64KB) into a slot ----------------
__device__ __forceinline__ void issue_layer_copy(uint32_t sb, int slot, int L, int tid) {
    const char* gsrc = (const char*)g_Wh + (size_t)L * 65536;
    uint32_t dstbase = sb + (uint32_t)slot * SLOT_BYTES;
    #pragma unroll
    for (int h = 0; h < 2; ++h)
        #pragma unroll
        for (int t = 0; t < 2; ++t)
            #pragma unroll
            for (int i = 0; i < 4; ++i) {
                int idx = i * 256 + tid;
                CP_ASYNC(dstbase + (uint32_t)(h * 32768 + t * 16384 + idx * 16),
                         gsrc + t * 32768 + h * 16384 + idx * 16);
            }
    CP_COMMIT();
}

// ---------------- MMA mainloop: 8 K-chunks over one 64KB slot ----------------
struct LaneCtx { uint32_t sb; int lane_row; int lane_cadd; };

__device__ __forceinline__ void do_layer_mma(uint32_t slotoff,
                                             const uint32_t* A, float* C00, uint32_t* C01h,
                                             const LaneCtx& lc) {
    #pragma unroll
    for (int qq = 0; qq < 8; ++qq) {
        int h = qq >> 2, rr = qq & 3;
        uint32_t rowaddr = lc.sb + slotoff + (uint32_t)h * 32768u
                         + (uint32_t)(rr * 16 + lc.lane_row) * 256u;
        #pragma unroll
        for (int jq = 0; jq < 4; ++jq) {
            uint32_t Bf[2][2][4];
            #pragma unroll
            for (int jp = 0; jp < 2; ++jp) {
                int c  = 2 * (2 * jq + jp) + lc.lane_cadd;
                int cp = c ^ lc.lane_row;
                uint32_t addr = rowaddr + (uint32_t)cp * 16u;
                ldsm4t(addr,          Bf[jp][0][0], Bf[jp][0][1], Bf[jp][0][2], Bf[jp][0][3]);
                ldsm4t(addr + 16384u, Bf[jp][1][0], Bf[jp][1][1], Bf[jp][1][2], Bf[jp][1][3]);
            }
            const uint32_t* A0 = A + qq * 8;
            const uint32_t* A1 = A0 + 4;
            #pragma unroll
            for (int cc = 0; cc < 4; ++cc) {
                int jp = cc >> 1, hf = cc & 1;
                float*    c00 = &C00[(4 * jq + cc) * 4];
                uint32_t* c01 = &C01h[(4 * jq + cc) * 2];
                uint32_t b00 = Bf[jp][0][hf * 2], b01 = Bf[jp][0][hf * 2 + 1];
                uint32_t b10 = Bf[jp][1][hf * 2], b11 = Bf[jp][1][hf * 2 + 1];
                mma_f16(c00, A0[0], A0[1], A0[2], A0[3], b00, b01);
                mma_f16acc(c01, A0[0], A0[1], A0[2], A0[3], b10, b11);
                mma_f16acc(c01, A1[0], A1[1], A1[2], A1[3], b00, b01);
            }
        }
    }
}

// ---------------- main kernel ----------------
__global__ void __launch_bounds__(NTHR, 1)
pairnet_mma(const float* __restrict__ R,
            const int*   __restrict__ idx_i,
            const int*   __restrict__ idx_j,
            const float* __restrict__ iB, const float* __restrict__ oB,
            const float* __restrict__ oWf, const float* __restrict__ oBf,
            float* __restrict__ outRij)
{
    extern __shared__ char smem[];
    uint32_t sb = smem_u32(smem);
    float* sBias = (float*)(smem + BIAS_OFF);
    float* sWf   = (float*)(smem + WF_OFF);
    float* sEr   = (float*)(smem + ER_OFF);
    float* sFc   = (float*)(smem + FC_OFF);
    int*   sIdx  = (int*)  (smem + IDX_OFF);
    uint4* sSpill = (uint4*)(smem + SPILL_OFF);

    const int tid = threadIdx.x;
    const int w = tid >> 5, l = tid & 31;
    const int g = l >> 2, four = l & 3;
    const int p0 = blockIdx.x * 128;
    LaneCtx lc; lc.sb = sb; lc.lane_row = l & 15; lc.lane_cadd = l >> 4;

    // prologue: stage layer 0 into slot 0
    issue_layer_copy(sb, 0, 0, tid);

    // geometry
    if (tid < 128) {
        int p = p0 + tid;
        float er = 0.0f, fc = 0.0f; int ii = 0;
        if (p < NP) {
            ii = idx_i[p];
            int jj = idx_j[p];
            float dx = R[3*jj+0] - R[3*ii+0];
            float dy = R[3*jj+1] - R[3*ii+1];
            float dz = R[3*jj+2] - R[3*ii+2];
            float rij = sqrtf(dx*dx + dy*dy + dz*dz + 1e-12f);
            outRij[p] = rij;
            if (rij < 10.0f) {
                float xq = rij * 0.1f;
                float x2 = xq*xq, x3 = x2*xq, x4 = x2*x2, x5 = x4*xq;
                fc = 1.0f - 6.0f*x5 + 15.0f*x4 - 10.0f*x3;
            }
            er = expf(-rij);
        }
        sIdx[tid] = ii; sEr[tid] = er; sFc[tid] = fc;
    }
    __syncthreads();

    // basis -> A fragments (2 limbs, registers)
    uint32_t A[64];
    {
        const float MU0    = 4.5399929762484854e-05f;
        const float MUSTEP = 7.8736582670224e-03f;
        const float WIDTH  = 4096.37195f;
        float er0 = sEr[16*w + g],     fc0 = sFc[16*w + g];
        float er8 = sEr[16*w + g + 8], fc8 = sFc[16*w + g + 8];
        #pragma unroll
        for (int q = 0; q < 8; ++q) {
            #pragma unroll
            for (int jj = 0; jj < 2; ++jj) {
                int k0 = 16*q + 8*jj + 2*four;
                float m0 = MU0 + (float)k0 * MUSTEP;
                float m1 = MU0 + (float)(k0+1) * MUSTEP;
                float d;
                d = er0 - m0; float e0 = fc0 * __expf(-WIDTH * d * d);
                d = er0 - m1; float e1 = fc0 * __expf(-WIDTH * d * d);
                d = er8 - m0; float e2 = fc8 * __expf(-WIDTH * d * d);
                d = er8 - m1; float e3 = fc8 * __expf(-WIDTH * d * d);
                split2h_pair(e0, e1, A[q*8 + jj*2 + 0], A[q*8 + 4 + jj*2 + 0]);
                split2h_pair(e2, e3, A[q*8 + jj*2 + 1], A[q*8 + 4 + jj*2 + 1]);
            }
        }
    }

    float C00[64];
    uint32_t C01h[32];

    #pragma unroll 1
    for (int L = 0; L < NLAYERS; ++L) {
        const int b = L >> 2, lay = L & 3;
        const int slot = L & 1;

        __syncthreads();   // all warps done reading slot (L+1)&1 (layer L-1 data)

        // stage bias / head weights for THIS layer (used after next sync)
        const float* bp = (lay < 2) ? iB + (b*2 + lay)*128 : oB + (b*2 + lay - 2)*128;
        if (tid < 128) sBias[tid] = bp[tid];
        if (lay == 3) sWf[tid] = oWf[b*256 + tid];

        // prefetch next layer into the other slot
        if (L < NLAYERS - 1) issue_layer_copy(sb, slot ^ 1, L + 1, tid);

        CP_WAIT(1);        // drain this layer's copy (issued a full layer ago)
        __syncthreads();   // make all threads' copies visible

        #pragma unroll
        for (int i = 0; i < 64; ++i) C00[i] = 0.0f;
        #pragma unroll
        for (int i = 0; i < 32; ++i) C01h[i] = 0u;

        do_layer_mma((uint32_t)slot * SLOT_BYTES, A, C00, C01h, lc);

        if (lay == 2) {   // spill x (per-thread round trip; no sync needed)
            #pragma unroll
            for (int i = 0; i < 16; ++i) sSpill[i * 256 + tid] = ((uint4*)A)[i];
        }

        if (lay < 3) {
            // epilogue: combine, bias + ssp, re-split -> new A
            #pragma unroll
            for (int q = 0; q < 8; ++q) {
                #pragma unroll
                for (int jj = 0; jj < 2; ++jj) {
                    int j = 2*q + jj;
                    float2 bb = *(const float2*)&sBias[j*8 + four*2];
                    float v[4];
                    combine4(&C00[j*4], &C01h[j*2], v);
                    float e0 = sspf(v[0] + bb.x);
                    float e1 = sspf(v[1] + bb.y);
                    float e2 = sspf(v[2] + bb.x);
                    float e3 = sspf(v[3] + bb.y);
                    split2h_pair(e0, e1, A[q*8 + jj*2 + 0], A[q*8 + 4 + jj*2 + 0]);
                    split2h_pair(e2, e3, A[q*8 + jj*2 + 1], A[q*8 + 4 + jj*2 + 1]);
                }
            }
        } else {
            // head: y2 = ssp(C + bias); out = y2 @ Wf + oBf; segment atomics
            float s00 = 0.f, s01 = 0.f, s10 = 0.f, s11 = 0.f;
            #pragma unroll
            for (int j = 0; j < 16; ++j) {
                int col0 = j*8 + four*2;
                float2 bb = *(const float2*)&sBias[col0];
                float v[4];
                combine4(&C00[j*4], &C01h[j*2], v);
                float e0 = sspf(v[0] + bb.x);
                float e1 = sspf(v[1] + bb.y);
                float e2 = sspf(v[2] + bb.x);
                float e3 = sspf(v[3] + bb.y);
                float2 w0 = *(const float2*)&sWf[col0*2];
                float2 w1 = *(const float2*)&sWf[col0*2 + 2];
                s00 = fmaf(e0, w0.x, fmaf(e1, w1.x, s00));
                s01 = fmaf(e0, w0.y, fmaf(e1, w1.y, s01));
                s10 = fmaf(e2, w0.x, fmaf(e3, w1.x, s10));
                s11 = fmaf(e2, w0.y, fmaf(e3, w1.y, s11));
            }
            #pragma unroll
            for (int d = 1; d <= 2; d <<= 1) {
                s00 += __shfl_xor_sync(0xffffffffu, s00, d);
                s01 += __shfl_xor_sync(0xffffffffu, s01, d);
                s10 += __shfl_xor_sync(0xffffffffu, s10, d);
                s11 += __shfl_xor_sync(0xffffffffu, s11, d);
            }
            if (four == 0) {
                float bf0 = __ldg(&oBf[b*2]), bf1 = __ldg(&oBf[b*2+1]);
                int r0 = 16*w + g, r1 = r0 + 8;
                if (p0 + r0 < NP) {
                    int a = sIdx[r0];
                    atomicAdd(&g_blockout[(b*NATOMS + a)*2 + 0], s00 + bf0);
                    atomicAdd(&g_blockout[(b*NATOMS + a)*2 + 1], s01 + bf1);
                }
                if (p0 + r1 < NP) {
                    int a = sIdx[r1];
                    atomicAdd(&g_blockout[(b*NATOMS + a)*2 + 0], s10 + bf0);
                    atomicAdd(&g_blockout[(b*NATOMS + a)*2 + 1], s11 + bf1);
                }
            }
            // restore x for next block
            if (L < NLAYERS - 1) {
                #pragma unroll
                for (int i = 0; i < 16; ++i) ((uint4*)A)[i] = sSpill[i * 256 + tid];
            }
        }
    }
}

// ---------------- zero / finalize ----------------
__global__ void zero_scratch() {
    int i = blockIdx.x * blockDim.x + threadIdx.x;
    if (i < NBLK * NATOMS * 2) g_blockout[i] = 0.0f;
    if (i == 0) g_nh = 0.0f;
}

__global__ void finalize_kernel(const int* __restrict__ Z,
                                const float* __restrict__ scales,
                                const float* __restrict__ shifts,
                                float* __restrict__ out)
{
    int a = blockIdx.x * blockDim.x + threadIdx.x;
    float local = 0.0f;
    if (a < NATOMS) {
        int z = Z[a];
        #pragma unroll
        for (int o = 0; o < 2; ++o) {
            float tot = 0.0f, last2 = 0.0f;
            #pragma unroll
            for (int b = 0; b < NBLK; ++b) {
                float v = g_blockout[(b * NATOMS + a) * 2 + o];
                tot += v;
                float v2 = v * v;
                if (b > 0) local += v2 / (v2 + last2 + 1e-7f);
                last2 = v2;
            }
            out[a * 2 + o] = tot * scales[o * 95 + z] + shifts[o * 95 + z];
        }
    }
    __shared__ float red[256];
    red[threadIdx.x] = local;
    __syncthreads();
    #pragma unroll
    for (int s = 128; s > 0; s >>= 1) {
        if (threadIdx.x < s) red[threadIdx.x] += red[threadIdx.x + s];
        __syncthreads();
    }
    if (threadIdx.x == 0) atomicAdd(&g_nh, red[0]);
}

__global__ void write_nh(float* __restrict__ out) {
    out[NATOMS * 2 + NP] = g_nh * (1.0f / 20000.0f);
}

// ---------------- launch ----------------
extern "C" void kernel_launch(void* const* d_in, const int* in_sizes, int n_in,
                              void* d_out, int out_size)
{
    const int*   Z      = (const int*)  d_in[0];
    const float* R      = (const float*)d_in[1];
    const int*   idx_i  = (const int*)  d_in[2];
    const int*   idx_j  = (const int*)  d_in[3];
    const float* iW     = (const float*)d_in[4];
    const float* iB     = (const float*)d_in[5];
    const float* oW     = (const float*)d_in[6];
    const float* oB     = (const float*)d_in[7];
    const float* oWf    = (const float*)d_in[8];
    const float* oBf    = (const float*)d_in[9];
    const float* scales = (const float*)d_in[10];
    const float* shifts = (const float*)d_in[11];
    float* out = (float*)d_out;

    cudaFuncSetAttribute(pairnet_mma,
                         cudaFuncAttributeMaxDynamicSharedMemorySize, SMEM_BYTES);

    zero_scratch<<<(NBLK * NATOMS * 2 + 255) / 256, 256>>>();
    split_weights<<<dim3(NLAYERS, 8), 256>>>(iW, oW);

    int nblocks = (NP + 127) / 128;   // 1954
    pairnet_mma<<<nblocks, NTHR, SMEM_BYTES>>>(
        R, idx_i, idx_j, iB, oB, oWf, oBf, out + 2 * NATOMS);

    finalize_kernel<<<(NATOMS + 255) / 256, 256>>>(Z, scales, shifts, out);
    write_nh<<<1, 1>>>(out);
}

// round 9
// speedup vs baseline: 3.0435x; 1.0530x over previous
#include <cuda_runtime.h>
#include <cuda_fp16.h>
#include <cstdint>

#define NP      250000
#define NATOMS  10000
#define NBLK    5
#define NLAYERS 20
#define NTHR    256

// packed layer = 64KB weights (2 limbs x 32KB) + 512B bias
#define LAYER_PACK  66048
#define SLOT_STRIDE 66560

// smem layout (bytes)
#define SPILL_OFF  133120
#define WFALL_OFF  198656
#define ER_OFF     203776
#define FC_OFF     204288
#define IDX_OFF    204800
#define MBAR_OFF   205312      // mbCopy0, mbCopy1, mbFree0, mbFree1 (8B each)
#define SMEM_BYTES 205824

#define INV2048 4.8828125e-4f

__device__ float g_blockout[NBLK * NATOMS * 2];
__device__ float g_nh;
// prepacked per layer: [limb0 32KB][limb1 32KB][bias 512B], swizzled n
__device__ __align__(16) char g_pack[NLAYERS * LAYER_PACK];

// ---------------- helpers ----------------
__device__ __forceinline__ uint32_t smem_u32(const void* p) {
    uint32_t a;
    asm("{ .reg .u64 t; cvta.to.shared.u64 t, %1; cvt.u32.u64 %0, t; }" : "=r"(a) : "l"(p));
    return a;
}
__device__ __forceinline__ void mma_f16(float* c, uint32_t a0, uint32_t a1, uint32_t a2, uint32_t a3,
                                        uint32_t b0, uint32_t b1) {
    asm volatile("mma.sync.aligned.m16n8k16.row.col.f32.f16.f16.f32 "
                 "{%0,%1,%2,%3}, {%4,%5,%6,%7}, {%8,%9}, {%0,%1,%2,%3};"
                 : "+f"(c[0]), "+f"(c[1]), "+f"(c[2]), "+f"(c[3])
                 : "r"(a0), "r"(a1), "r"(a2), "r"(a3), "r"(b0), "r"(b1));
}
__device__ __forceinline__ void mma_f16acc(uint32_t* c, uint32_t a0, uint32_t a1, uint32_t a2, uint32_t a3,
                                           uint32_t b0, uint32_t b1) {
    asm volatile("mma.sync.aligned.m16n8k16.row.col.f16.f16.f16.f16 "
                 "{%0,%1}, {%2,%3,%4,%5}, {%6,%7}, {%0,%1};"
                 : "+r"(c[0]), "+r"(c[1])
                 : "r"(a0), "r"(a1), "r"(a2), "r"(a3), "r"(b0), "r"(b1));
}
__device__ __forceinline__ void ldsm4t(uint32_t addr, uint32_t& r0, uint32_t& r1, uint32_t& r2, uint32_t& r3) {
    asm volatile("ldmatrix.sync.aligned.m8n8.x4.trans.shared.b16 {%0,%1,%2,%3}, [%4];"
                 : "=r"(r0), "=r"(r1), "=r"(r2), "=r"(r3) : "r"(addr));
}
#define CP_ASYNC(dst, src) asm volatile("cp.async.cg.shared.global [%0], [%1], 16;" :: "r"(dst), "l"(src) : "memory")
#define MBAR_INIT(sa, c)   asm volatile("mbarrier.init.shared.b64 [%0], %1;" :: "r"(sa), "r"(c) : "memory")
#define MBAR_ARRIVE(sa)    asm volatile("mbarrier.arrive.shared.b64 _, [%0];" :: "r"(sa) : "memory")
// .noinc: each thread contributes ONE arrival (at async-copy completion) against
// the init count — the non-noinc form is self-balancing and never flips the phase.
#define CPASYNC_MBAR_ARRIVE(sa) asm volatile("cp.async.mbarrier.arrive.noinc.shared.b64 [%0];" :: "r"(sa) : "memory")
#define MBAR_WAIT(sa, ph) do { \
    asm volatile("{ .reg .pred P1; WL%=: mbarrier.try_wait.parity.shared.b64 P1, [%0], %1; @P1 bra.uni WD%=; bra.uni WL%=; WD%=: }" \
        :: "r"(sa), "r"(ph) : "memory"); \
} while (0)

// fast ssp (pre-acts are O(1); clamp is inf-guard)
__device__ __forceinline__ float sspf(float x) {
    float e = __expf(fminf(x, 60.0f));
    return __logf(1.0f + e) - 0.69314718055994531f;
}
__device__ __forceinline__ void split2h_pair(float v0, float v1, uint32_t& u0, uint32_t& u1) {
    __half2 h0 = __float22half2_rn(make_float2(v0, v1));
    u0 = *reinterpret_cast<uint32_t*>(&h0);
    float2 f = __half22float2(h0);
    __half2 h1 = __float22half2_rn(make_float2((v0 - f.x) * 2048.0f, (v1 - f.y) * 2048.0f));
    u1 = *reinterpret_cast<uint32_t*>(&h1);
}
__device__ __forceinline__ void combine4(const float* c00, const uint32_t* c01h, float* v) {
    float2 lo = __half22float2(*reinterpret_cast<const __half2*>(&c01h[0]));
    float2 hi = __half22float2(*reinterpret_cast<const __half2*>(&c01h[1]));
    v[0] = fmaf(lo.x, INV2048, c00[0]);
    v[1] = fmaf(lo.y, INV2048, c00[1]);
    v[2] = fmaf(hi.x, INV2048, c00[2]);
    v[3] = fmaf(hi.y, INV2048, c00[3]);
}

// ---------------- weight prep: split + swizzle + bias append ----------------
__global__ void split_weights(const float* __restrict__ iW, const float* __restrict__ oW,
                              const float* __restrict__ iB, const float* __restrict__ oB) {
    int L = blockIdx.x, sl = blockIdx.y;
    int b = L >> 2, l = L & 3;
    const float* W = (l < 2) ? iW + (size_t)(b * 2 + l) * 16384
                             : oW + (size_t)(b * 2 + l - 2) * 16384;
    __half* wdst = (__half*)(g_pack + (size_t)L * LAYER_PACK);
    for (int e = sl * 2048 + threadIdx.x; e < (sl + 1) * 2048; e += 256) {
        int k = e >> 7, n = e & 127;
        float v = W[e];
        __half h0 = __float2half_rn(v);
        __half h1 = __float2half_rn((v - __half2float(h0)) * 2048.0f);
        int c = (n >> 3) ^ (k & 15);
        int idx = k * 128 + c * 8 + (n & 7);
        wdst[idx]         = h0;
        wdst[16384 + idx] = h1;
    }
    if (sl == 0 && threadIdx.x < 128) {
        const float* bp = (l < 2) ? iB + (b * 2 + l) * 128 : oB + (b * 2 + l - 2) * 128;
        ((float*)(g_pack + (size_t)L * LAYER_PACK + 65536))[threadIdx.x] = bp[threadIdx.x];
    }
}

// ---------------- issue one layer copy (weights+bias) into a slot ----------------
__device__ __forceinline__ void issue_layer_copy(uint32_t sb, int slot, int L, int tid,
                                                 uint32_t mbCopyAddr) {
    const char* gsrc = g_pack + (size_t)L * LAYER_PACK;
    uint32_t dst = sb + (uint32_t)slot * SLOT_STRIDE;
    #pragma unroll
    for (int h = 0; h < 2; ++h)
        #pragma unroll
        for (int t = 0; t < 2; ++t)
            #pragma unroll
            for (int i = 0; i < 4; ++i) {
                int idx = i * 256 + tid;
                CP_ASYNC(dst + (uint32_t)(h * 32768 + t * 16384 + idx * 16),
                         gsrc + t * 32768 + h * 16384 + idx * 16);
            }
    if (tid < 32) CP_ASYNC(dst + 65536 + (uint32_t)tid * 16, gsrc + 65536 + tid * 16);
    CPASYNC_MBAR_ARRIVE(mbCopyAddr);
}

// ---------------- MMA mainloop: 8 K-chunks over one slot ----------------
struct LaneCtx { uint32_t sb; int lane_row; int lane_cadd; };

__device__ __forceinline__ void do_layer_mma(uint32_t slotoff,
                                             const uint32_t* A, float* C00, uint32_t* C01h,
                                             const LaneCtx& lc) {
    #pragma unroll
    for (int qq = 0; qq < 8; ++qq) {
        int h = qq >> 2, rr = qq & 3;
        uint32_t rowaddr = lc.sb + slotoff + (uint32_t)h * 32768u
                         + (uint32_t)(rr * 16 + lc.lane_row) * 256u;
        #pragma unroll
        for (int jq = 0; jq < 4; ++jq) {
            uint32_t Bf[2][2][4];
            #pragma unroll
            for (int jp = 0; jp < 2; ++jp) {
                int c  = 2 * (2 * jq + jp) + lc.lane_cadd;
                int cp = c ^ lc.lane_row;
                uint32_t addr = rowaddr + (uint32_t)cp * 16u;
                ldsm4t(addr,          Bf[jp][0][0], Bf[jp][0][1], Bf[jp][0][2], Bf[jp][0][3]);
                ldsm4t(addr + 16384u, Bf[jp][1][0], Bf[jp][1][1], Bf[jp][1][2], Bf[jp][1][3]);
            }
            const uint32_t* A0 = A + qq * 8;
            const uint32_t* A1 = A0 + 4;
            #pragma unroll
            for (int cc = 0; cc < 4; ++cc) {
                int jp = cc >> 1, hf = cc & 1;
                float*    c00 = &C00[(4 * jq + cc) * 4];
                uint32_t* c01 = &C01h[(4 * jq + cc) * 2];
                uint32_t b00 = Bf[jp][0][hf * 2], b01 = Bf[jp][0][hf * 2 + 1];
                uint32_t b10 = Bf[jp][1][hf * 2], b11 = Bf[jp][1][hf * 2 + 1];
                mma_f16(c00, A0[0], A0[1], A0[2], A0[3], b00, b01);
                mma_f16acc(c01, A0[0], A0[1], A0[2], A0[3], b10, b11);
                mma_f16acc(c01, A1[0], A1[1], A1[2], A1[3], b00, b01);
            }
        }
    }
}

// ---------------- main kernel ----------------
__global__ void __launch_bounds__(NTHR, 1)
pairnet_mma(const float* __restrict__ R,
            const int*   __restrict__ idx_i,
            const int*   __restrict__ idx_j,
            const float* __restrict__ oWf, const float* __restrict__ oBf,
            float* __restrict__ outRij)
{
    extern __shared__ char smem[];
    uint32_t sb = smem_u32(smem);
    float* sWfAll = (float*)(smem + WFALL_OFF);
    float* sEr    = (float*)(smem + ER_OFF);
    float* sFc    = (float*)(smem + FC_OFF);
    int*   sIdx   = (int*)  (smem + IDX_OFF);
    uint4* sSpill = (uint4*)(smem + SPILL_OFF);
    uint32_t mbCopy0 = sb + MBAR_OFF,      mbCopy1 = sb + MBAR_OFF + 8;
    uint32_t mbFree0 = sb + MBAR_OFF + 16, mbFree1 = sb + MBAR_OFF + 24;

    const int tid = threadIdx.x;
    const int w = tid >> 5, l = tid & 31;
    const int g = l >> 2, four = l & 3;
    const int p0 = blockIdx.x * 128;
    LaneCtx lc; lc.sb = sb; lc.lane_row = l & 15; lc.lane_cadd = l >> 4;

    if (tid == 0) {
        MBAR_INIT(mbCopy0, NTHR); MBAR_INIT(mbCopy1, NTHR);
        MBAR_INIT(mbFree0, NTHR); MBAR_INIT(mbFree1, NTHR);
    }
    __syncthreads();

    // prologue: stage layers 0 and 1
    issue_layer_copy(sb, 0, 0, tid, mbCopy0);
    issue_layer_copy(sb, 1, 1, tid, mbCopy1);

    // geometry
    if (tid < 128) {
        int p = p0 + tid;
        float er = 0.0f, fc = 0.0f; int ii = 0;
        if (p < NP) {
            ii = idx_i[p];
            int jj = idx_j[p];
            float dx = R[3*jj+0] - R[3*ii+0];
            float dy = R[3*jj+1] - R[3*ii+1];
            float dz = R[3*jj+2] - R[3*ii+2];
            float rij = sqrtf(dx*dx + dy*dy + dz*dz + 1e-12f);
            outRij[p] = rij;
            if (rij < 10.0f) {
                float xq = rij * 0.1f;
                float x2 = xq*xq, x3 = x2*xq, x4 = x2*x2, x5 = x4*xq;
                fc = 1.0f - 6.0f*x5 + 15.0f*x4 - 10.0f*x3;
            }
            er = expf(-rij);
        }
        sIdx[tid] = ii; sEr[tid] = er; sFc[tid] = fc;
    }
    // head weights for all 5 blocks (once)
    for (int i = tid; i < 1280; i += NTHR) sWfAll[i] = oWf[i];
    __syncthreads();

    // basis -> A fragments
    uint32_t A[64];
    {
        const float MU0    = 4.5399929762484854e-05f;
        const float MUSTEP = 7.8736582670224e-03f;
        const float WIDTH  = 4096.37195f;
        float er0 = sEr[16*w + g],     fc0 = sFc[16*w + g];
        float er8 = sEr[16*w + g + 8], fc8 = sFc[16*w + g + 8];
        #pragma unroll
        for (int q = 0; q < 8; ++q) {
            #pragma unroll
            for (int jj = 0; jj < 2; ++jj) {
                int k0 = 16*q + 8*jj + 2*four;
                float m0 = MU0 + (float)k0 * MUSTEP;
                float m1 = MU0 + (float)(k0+1) * MUSTEP;
                float d;
                d = er0 - m0; float e0 = fc0 * __expf(-WIDTH * d * d);
                d = er0 - m1; float e1 = fc0 * __expf(-WIDTH * d * d);
                d = er8 - m0; float e2 = fc8 * __expf(-WIDTH * d * d);
                d = er8 - m1; float e3 = fc8 * __expf(-WIDTH * d * d);
                split2h_pair(e0, e1, A[q*8 + jj*2 + 0], A[q*8 + 4 + jj*2 + 0]);
                split2h_pair(e2, e3, A[q*8 + jj*2 + 1], A[q*8 + 4 + jj*2 + 1]);
            }
        }
    }

    float C00[64];
    uint32_t C01h[32];

    #pragma unroll 1
    for (int L = 0; L < NLAYERS; ++L) {
        const int b = L >> 2, lay = L & 3;
        const int slot = L & 1;
        const uint32_t slotoff = (uint32_t)slot * SLOT_STRIDE;

        // gate + issue copy for layer L+1 into the other slot
        if (L >= 1 && L < NLAYERS - 1) {
            MBAR_WAIT((slot ? mbFree0 : mbFree1), ((L - 1) >> 1) & 1);
            issue_layer_copy(sb, slot ^ 1, L + 1, tid, (slot ? mbCopy0 : mbCopy1));
        }

        // wait for this layer's weights
        MBAR_WAIT((slot ? mbCopy1 : mbCopy0), (L >> 1) & 1);

        #pragma unroll
        for (int i = 0; i < 64; ++i) C00[i] = 0.0f;
        #pragma unroll
        for (int i = 0; i < 32; ++i) C01h[i] = 0u;

        do_layer_mma(slotoff, A, C00, C01h, lc);

        // done reading this slot
        MBAR_ARRIVE((slot ? mbFree1 : mbFree0));

        const float* bias = (const float*)(smem + slotoff + 65536);

        if (lay == 2) {   // spill x (per-thread private round trip)
            #pragma unroll
            for (int i = 0; i < 16; ++i) sSpill[i * 256 + tid] = ((uint4*)A)[i];
        }

        if (lay < 3) {
            #pragma unroll
            for (int q = 0; q < 8; ++q) {
                #pragma unroll
                for (int jj = 0; jj < 2; ++jj) {
                    int j = 2*q + jj;
                    float2 bb = *(const float2*)&bias[j*8 + four*2];
                    float v[4];
                    combine4(&C00[j*4], &C01h[j*2], v);
                    float e0 = sspf(v[0] + bb.x);
                    float e1 = sspf(v[1] + bb.y);
                    float e2 = sspf(v[2] + bb.x);
                    float e3 = sspf(v[3] + bb.y);
                    split2h_pair(e0, e1, A[q*8 + jj*2 + 0], A[q*8 + 4 + jj*2 + 0]);
                    split2h_pair(e2, e3, A[q*8 + jj*2 + 1], A[q*8 + 4 + jj*2 + 1]);
                }
            }
        } else {
            const float* wf = sWfAll + b * 256;
            float s00 = 0.f, s01 = 0.f, s10 = 0.f, s11 = 0.f;
            #pragma unroll
            for (int j = 0; j < 16; ++j) {
                int col0 = j*8 + four*2;
                float2 bb = *(const float2*)&bias[col0];
                float v[4];
                combine4(&C00[j*4], &C01h[j*2], v);
                float e0 = sspf(v[0] + bb.x);
                float e1 = sspf(v[1] + bb.y);
                float e2 = sspf(v[2] + bb.x);
                float e3 = sspf(v[3] + bb.y);
                float2 w0 = *(const float2*)&wf[col0*2];
                float2 w1 = *(const float2*)&wf[col0*2 + 2];
                s00 = fmaf(e0, w0.x, fmaf(e1, w1.x, s00));
                s01 = fmaf(e0, w0.y, fmaf(e1, w1.y, s01));
                s10 = fmaf(e2, w0.x, fmaf(e3, w1.x, s10));
                s11 = fmaf(e2, w0.y, fmaf(e3, w1.y, s11));
            }
            #pragma unroll
            for (int d = 1; d <= 2; d <<= 1) {
                s00 += __shfl_xor_sync(0xffffffffu, s00, d);
                s01 += __shfl_xor_sync(0xffffffffu, s01, d);
                s10 += __shfl_xor_sync(0xffffffffu, s10, d);
                s11 += __shfl_xor_sync(0xffffffffu, s11, d);
            }
            if (four == 0) {
                float bf0 = __ldg(&oBf[b*2]), bf1 = __ldg(&oBf[b*2+1]);
                int r0 = 16*w + g, r1 = r0 + 8;
                if (p0 + r0 < NP) {
                    int a = sIdx[r0];
                    atomicAdd(&g_blockout[(b*NATOMS + a)*2 + 0], s00 + bf0);
                    atomicAdd(&g_blockout[(b*NATOMS + a)*2 + 1], s01 + bf1);
                }
                if (p0 + r1 < NP) {
                    int a = sIdx[r1];
                    atomicAdd(&g_blockout[(b*NATOMS + a)*2 + 0], s10 + bf0);
                    atomicAdd(&g_blockout[(b*NATOMS + a)*2 + 1], s11 + bf1);
                }
            }
            if (L < NLAYERS - 1) {   // restore x
                #pragma unroll
                for (int i = 0; i < 16; ++i) ((uint4*)A)[i] = sSpill[i * 256 + tid];
            }
        }
    }
}

// ---------------- zero / finalize ----------------
__global__ void zero_scratch() {
    int i = blockIdx.x * blockDim.x + threadIdx.x;
    if (i < NBLK * NATOMS * 2) g_blockout[i] = 0.0f;
    if (i == 0) g_nh = 0.0f;
}

__global__ void finalize_kernel(const int* __restrict__ Z,
                                const float* __restrict__ scales,
                                const float* __restrict__ shifts,
                                float* __restrict__ out)
{
    int a = blockIdx.x * blockDim.x + threadIdx.x;
    float local = 0.0f;
    if (a < NATOMS) {
        int z = Z[a];
        #pragma unroll
        for (int o = 0; o < 2; ++o) {
            float tot = 0.0f, last2 = 0.0f;
            #pragma unroll
            for (int b = 0; b < NBLK; ++b) {
                float v = g_blockout[(b * NATOMS + a) * 2 + o];
                tot += v;
                float v2 = v * v;
                if (b > 0) local += v2 / (v2 + last2 + 1e-7f);
                last2 = v2;
            }
            out[a * 2 + o] = tot * scales[o * 95 + z] + shifts[o * 95 + z];
        }
    }
    __shared__ float red[256];
    red[threadIdx.x] = local;
    __syncthreads();
    #pragma unroll
    for (int s = 128; s > 0; s >>= 1) {
        if (threadIdx.x < s) red[threadIdx.x] += red[threadIdx.x + s];
        __syncthreads();
    }
    if (threadIdx.x == 0) atomicAdd(&g_nh, red[0]);
}

__global__ void write_nh(float* __restrict__ out) {
    out[NATOMS * 2 + NP] = g_nh * (1.0f / 20000.0f);
}

// ---------------- launch ----------------
extern "C" void kernel_launch(void* const* d_in, const int* in_sizes, int n_in,
                              void* d_out, int out_size)
{
    const int*   Z      = (const int*)  d_in[0];
    const float* R      = (const float*)d_in[1];
    const int*   idx_i  = (const int*)  d_in[2];
    const int*   idx_j  = (const int*)  d_in[3];
    const float* iW     = (const float*)d_in[4];
    const float* iB     = (const float*)d_in[5];
    const float* oW     = (const float*)d_in[6];
    const float* oB     = (const float*)d_in[7];
    const float* oWf    = (const float*)d_in[8];
    const float* oBf    = (const float*)d_in[9];
    const float* scales = (const float*)d_in[10];
    const float* shifts = (const float*)d_in[11];
    float* out = (float*)d_out;

    cudaFuncSetAttribute(pairnet_mma,
                         cudaFuncAttributeMaxDynamicSharedMemorySize, SMEM_BYTES);

    zero_scratch<<<(NBLK * NATOMS * 2 + 255) / 256, 256>>>();
    split_weights<<<dim3(NLAYERS, 8), 256>>>(iW, oW, iB, oB);

    int nblocks = (NP + 127) / 128;   // 1954
    pairnet_mma<<<nblocks, NTHR, SMEM_BYTES>>>(
        R, idx_i, idx_j, oWf, oBf, out + 2 * NATOMS);

    finalize_kernel<<<(NATOMS + 255) / 256, 256>>>(Z, scales, shifts, out);
    write_nh<<<1, 1>>>(out);
}